// round 1
// baseline (speedup 1.0000x reference)
#include <cuda_runtime.h>
#include <math.h>
#include <float.h>

#define Bz 8
#define Cc 192
#define Nn 1568
#define BNN (Bz*Nn)   /* 12544 */
#define KK 9

// ---------------- scratch (static device globals; no allocation) ----------------
__device__ float d_xfT[BNN*Cc];            // xf, node-major [j][c]
__device__ float d_xnT[BNN*Cc];            // normalized xf, node-major
__device__ float d_sq[BNN];                // sum(xn^2) per node
__device__ float d_dist[Bz*Nn*Nn];         // 78.7 MB distance matrix
__device__ int   d_nn[BNN*KK];             // knn indices (per-batch local)
__device__ float d_WUV[768*Cc];            // rows 0..383: We[:, :C]-We[:, C:]; 384..767: We[:, C:]
__device__ float d_W1s[Cc*384];            // BN1-folded W1
__device__ float d_W2s[Cc*Cc];             // BN2-folded W2
__device__ float d_c1[Cc];                 // b1*s1 + bn1_b
__device__ float d_c2[Cc];
__device__ float d_Yt[BNN*768];            // [j][0..383]=U, [j][384..767]=V
__device__ float d_gt[BNN*384];            // g (max-pooled edge features), node-major
__device__ float d_ht[BNN*Cc];             // h (shortcut), node-major

// ---------------- weight folding ----------------
__global__ void prep_w(const float* __restrict__ We, const float* __restrict__ W1,
                       const float* __restrict__ b1, const float* __restrict__ g1,
                       const float* __restrict__ bb1, const float* __restrict__ W2,
                       const float* __restrict__ b2, const float* __restrict__ g2,
                       const float* __restrict__ bb2)
{
    int i = blockIdx.x*blockDim.x + threadIdx.x;
    const float denom = (float)sqrt(1.0 + 1e-5);
    if (i < 768*Cc) {
        int o = i/Cc, c = i - o*Cc;
        d_WUV[i] = (o < 384) ? (We[o*384 + c] - We[o*384 + 192 + c])
                             : We[(o-384)*384 + 192 + c];
    }
    if (i < Cc*384) {
        int o = i/384;
        d_W1s[i] = W1[i] * (g1[o]/denom);
    }
    if (i < Cc*Cc) {
        int o = i/Cc;
        d_W2s[i] = W2[i] * (g2[o]/denom);
    }
    if (i < Cc) {
        d_c1[i] = b1[i]*(g1[i]/denom) + bb1[i];
        d_c2[i] = b2[i]*(g2[i]/denom) + bb2[i];
    }
}

// ---------------- xf = x + pos^T, normalize, sq ----------------
__global__ void prep_xf(const float* __restrict__ x, const float* __restrict__ pos)
{
    int j = blockIdx.x;               // node index 0..BNN-1
    int b = j / Nn, n = j - b*Nn;
    int c = threadIdx.x;              // 192 threads
    float v = x[((size_t)b*Cc + c)*Nn + n] + pos[n*Cc + c];
    d_xfT[(size_t)j*Cc + c] = v;

    __shared__ float red[Cc];
    __shared__ float s_nrm;
    red[c] = v*v;
    __syncthreads();
    if (c < 64) red[c] += red[c+64] + red[c+128];
    __syncthreads();
    if (c < 32) {
        float s = red[c] + red[c+32];
        #pragma unroll
        for (int o = 16; o; o >>= 1) s += __shfl_xor_sync(0xffffffffu, s, o);
        if (c == 0) s_nrm = fmaxf(sqrtf(s), 1e-12f);
    }
    __syncthreads();
    float xn = v / s_nrm;
    d_xnT[(size_t)j*Cc + c] = xn;

    red[c] = xn*xn;
    __syncthreads();
    if (c < 64) red[c] += red[c+64] + red[c+128];
    __syncthreads();
    if (c < 32) {
        float s = red[c] + red[c+32];
        #pragma unroll
        for (int o = 16; o; o >>= 1) s += __shfl_xor_sync(0xffffffffu, s, o);
        if (c == 0) d_sq[j] = s;
    }
}

// ---------------- NT GEMM template: C[m][n] = dot(Arow_m, Brow_n) ----------------
// MODE 0: gram -> dist  (per-batch, A=B=xn rows, epilogue sq_n - 2*acc + sq_m)
// MODE 1: Yt = xf . WUV^T            (M=12544, N=768, K=192)
// MODE 2: h  = relu(g . W1s^T + c1)  (M=12544, N=192, K=384)
// MODE 3: out= relu(h . W2s^T + c2) + h, scattered to [B,C,N] layout
template<int MODE>
__global__ void __launch_bounds__(256) gemm_nt(float* __restrict__ outp)
{
    constexpr int KDIM = (MODE==2) ? 384 : 192;
    constexpr int M    = (MODE==0) ? Nn  : BNN;
    constexpr int NC   = (MODE==0) ? Nn  : ((MODE==1) ? 768 : Cc);

    const float* A; const float* B;
    int z = blockIdx.z;
    if (MODE==0)      { A = d_xnT + (size_t)z*Nn*Cc; B = A; }
    else if (MODE==1) { A = d_xfT; B = d_WUV; }
    else if (MODE==2) { A = d_gt;  B = d_W1s; }
    else              { A = d_ht;  B = d_W2s; }

    __shared__ __align__(16) float As[16][132];
    __shared__ __align__(16) float Bs[16][132];

    int tid  = threadIdx.x;
    int row0 = blockIdx.y*128, col0 = blockIdx.x*128;
    int lr = tid >> 2;
    int lk = (tid & 3) << 2;
    int tx = tid & 15, ty = tid >> 4;

    float acc[8][8];
    #pragma unroll
    for (int i = 0; i < 8; i++)
        #pragma unroll
        for (int jj = 0; jj < 8; jj++) acc[i][jj] = 0.0f;

    for (int k0 = 0; k0 < KDIM; k0 += 16) {
        #pragma unroll
        for (int rr = 0; rr < 2; rr++) {
            int r  = lr + rr*64;
            int gr = row0 + r;
            float4 va = make_float4(0.f,0.f,0.f,0.f);
            if (gr < M) va = *reinterpret_cast<const float4*>(&A[(size_t)gr*KDIM + k0 + lk]);
            As[lk+0][r]=va.x; As[lk+1][r]=va.y; As[lk+2][r]=va.z; As[lk+3][r]=va.w;
            int gc = col0 + r;
            float4 vb = make_float4(0.f,0.f,0.f,0.f);
            if (gc < NC) vb = *reinterpret_cast<const float4*>(&B[(size_t)gc*KDIM + k0 + lk]);
            Bs[lk+0][r]=vb.x; Bs[lk+1][r]=vb.y; Bs[lk+2][r]=vb.z; Bs[lk+3][r]=vb.w;
        }
        __syncthreads();
        #pragma unroll
        for (int kk = 0; kk < 16; kk++) {
            float a[8], b[8];
            *reinterpret_cast<float4*>(&a[0]) = *reinterpret_cast<const float4*>(&As[kk][ty*8]);
            *reinterpret_cast<float4*>(&a[4]) = *reinterpret_cast<const float4*>(&As[kk][ty*8+4]);
            *reinterpret_cast<float4*>(&b[0]) = *reinterpret_cast<const float4*>(&Bs[kk][tx*8]);
            *reinterpret_cast<float4*>(&b[4]) = *reinterpret_cast<const float4*>(&Bs[kk][tx*8+4]);
            #pragma unroll
            for (int i = 0; i < 8; i++)
                #pragma unroll
                for (int jj = 0; jj < 8; jj++)
                    acc[i][jj] = fmaf(a[i], b[jj], acc[i][jj]);
        }
        __syncthreads();
    }

    if (MODE == 0) {
        const float* sq = d_sq + z*Nn;
        float* dst = d_dist + (size_t)z*Nn*Nn;
        #pragma unroll
        for (int i = 0; i < 8; i++) {
            int gr = row0 + ty*8 + i;
            if (gr < Nn) {
                float sn = sq[gr];
                #pragma unroll
                for (int jj = 0; jj < 8; jj++) {
                    int gc = col0 + tx*8 + jj;
                    if (gc < Nn)
                        dst[(size_t)gr*Nn + gc] = (sn - 2.0f*acc[i][jj]) + sq[gc];
                }
            }
        }
    } else if (MODE == 1) {
        #pragma unroll
        for (int i = 0; i < 8; i++) {
            int gr = row0 + ty*8 + i;
            #pragma unroll
            for (int jj = 0; jj < 8; jj++) {
                int gc = col0 + tx*8 + jj;
                if (gr < BNN && gc < 768) d_Yt[(size_t)gr*768 + gc] = acc[i][jj];
            }
        }
    } else if (MODE == 2) {
        #pragma unroll
        for (int i = 0; i < 8; i++) {
            int gr = row0 + ty*8 + i;
            #pragma unroll
            for (int jj = 0; jj < 8; jj++) {
                int gc = col0 + tx*8 + jj;
                if (gr < BNN && gc < Cc)
                    d_ht[(size_t)gr*Cc + gc] = fmaxf(acc[i][jj] + d_c1[gc], 0.0f);
            }
        }
    } else {
        #pragma unroll
        for (int i = 0; i < 8; i++) {
            int gr = row0 + ty*8 + i;
            if (gr < BNN) {
                int b = gr / Nn, n = gr - b*Nn;
                #pragma unroll
                for (int jj = 0; jj < 8; jj++) {
                    int gc = col0 + tx*8 + jj;
                    if (gc < Cc)
                        outp[((size_t)b*Cc + gc)*Nn + n] =
                            fmaxf(acc[i][jj] + d_c2[gc], 0.0f) + d_ht[(size_t)gr*Cc + gc];
                }
            }
        }
    }
}

// ---------------- top-9 smallest dist per row (lex tie-break: lower index) ----------------
__global__ void topk9()
{
    int lane = threadIdx.x & 31;
    int row  = blockIdx.x*4 + (threadIdx.x >> 5);
    if (row >= BNN) return;
    const float* dr = d_dist + (size_t)row*Nn;

    float bd[9]; int bi[9];
    #pragma unroll
    for (int s = 0; s < 9; s++) { bd[s] = FLT_MAX; bi[s] = 0x7fffffff; }
    float wd = FLT_MAX; int wi = 0x7fffffff; int ws = 0;

    for (int m = lane; m < Nn; m += 32) {
        float v = dr[m];
        if (v < wd || (v == wd && m < wi)) {
            #pragma unroll
            for (int s = 0; s < 9; s++) if (s == ws) { bd[s] = v; bi[s] = m; }
            wd = bd[0]; wi = bi[0]; ws = 0;
            #pragma unroll
            for (int s = 1; s < 9; s++)
                if (bd[s] > wd || (bd[s] == wd && bi[s] > wi)) { wd = bd[s]; wi = bi[s]; ws = s; }
        }
    }

    unsigned used = 0;
    for (int r = 0; r < 9; r++) {
        float lv = FLT_MAX; int li = 0x7fffffff;
        #pragma unroll
        for (int s = 0; s < 9; s++) {
            if (!((used >> s) & 1)) {
                if (bd[s] < lv || (bd[s] == lv && bi[s] < li)) { lv = bd[s]; li = bi[s]; }
            }
        }
        #pragma unroll
        for (int off = 16; off; off >>= 1) {
            float ov = __shfl_xor_sync(0xffffffffu, lv, off);
            int   oi = __shfl_xor_sync(0xffffffffu, li, off);
            if (ov < lv || (ov == lv && oi < li)) { lv = ov; li = oi; }
        }
        #pragma unroll
        for (int s = 0; s < 9; s++) if (bi[s] == li) used |= (1u << s);
        if (lane == 0) d_nn[row*9 + r] = li;
    }
}

// ---------------- g = relu(U + be + max_k V[idx]) ----------------
__global__ void gather_max(const float* __restrict__ be)
{
    int j = blockIdx.x;
    int o = threadIdx.x;      // 384 threads
    int b = j / Nn;
    int base = b*Nn;
    int id[9];
    #pragma unroll
    for (int k = 0; k < 9; k++) id[k] = d_nn[j*9 + k];
    float m = -FLT_MAX;
    #pragma unroll
    for (int k = 0; k < 9; k++)
        m = fmaxf(m, d_Yt[(size_t)(base + id[k])*768 + 384 + o]);
    float u = d_Yt[(size_t)j*768 + o] + be[o];
    d_gt[(size_t)j*384 + o] = fmaxf(u + m, 0.0f);
}

// ---------------- launch ----------------
extern "C" void kernel_launch(void* const* d_in, const int* in_sizes, int n_in,
                              void* d_out, int out_size)
{
    const float* x   = (const float*)d_in[0];
    const float* pos = (const float*)d_in[1];
    const float* We  = (const float*)d_in[2];
    const float* be  = (const float*)d_in[3];
    const float* W1  = (const float*)d_in[4];
    const float* b1  = (const float*)d_in[5];
    const float* g1  = (const float*)d_in[6];
    const float* bb1 = (const float*)d_in[7];
    const float* W2  = (const float*)d_in[8];
    const float* b2  = (const float*)d_in[9];
    const float* g2  = (const float*)d_in[10];
    const float* bb2 = (const float*)d_in[11];
    float* out = (float*)d_out;

    prep_w<<<576, 256>>>(We, W1, b1, g1, bb1, W2, b2, g2, bb2);
    prep_xf<<<BNN, 192>>>(x, pos);
    { dim3 g(13, 13, 8); gemm_nt<0><<<g, 256>>>(nullptr); }   // dist
    topk9<<<3136, 128>>>();
    { dim3 g(6, 98, 1);  gemm_nt<1><<<g, 256>>>(nullptr); }   // U,V
    gather_max<<<BNN, 384>>>(be);
    { dim3 g(2, 98, 1);  gemm_nt<2><<<g, 256>>>(nullptr); }   // h
    { dim3 g(2, 98, 1);  gemm_nt<3><<<g, 256>>>(out); }       // out
}

// round 2
// speedup vs baseline: 1.6006x; 1.6006x over previous
#include <cuda_runtime.h>
#include <math.h>
#include <float.h>

#define Bz 8
#define Cc 192
#define Nn 1568
#define NP 1664            /* padded N: 13*128 */
#define BNN (Bz*Nn)        /* 12544 */
#define KK 9
#define NBLK 13            /* NP/128 */

// ---------------- scratch (static device globals; no allocation) ----------------
__device__ float d_xfT[BNN*Cc];              // xf, node-major [j][c]
__device__ float d_xnp[Bz*NP*Cc];            // normalized xf, padded per batch
__device__ float d_sqp[Bz*NP];               // |xn|^2, pad rows = 1e30
__device__ float d_dist[(size_t)Bz*NP*NP];   // padded distance matrix (88.6 MB)
__device__ int   d_nn[BNN*KK];               // knn indices (per-batch local, unordered)
__device__ float d_WUV[768*Cc];              // rows 0..383: We[:, :C]-We[:, C:]; 384..767: We[:, C:]
__device__ float d_W1s[256*384];             // BN1-folded W1, zero-padded rows 192..255
__device__ float d_W2s[256*192];             // BN2-folded W2, zero-padded rows 192..255
__device__ float d_c1[Cc];
__device__ float d_c2[Cc];
__device__ float d_Yt[(size_t)BNN*768];      // [j][0..383]=U, [j][384..767]=V
__device__ float d_gt[(size_t)BNN*384];      // g, node-major
__device__ float d_ht[(size_t)BNN*Cc];       // h (shortcut), node-major

// ---------------- weight folding ----------------
__global__ void prep_w(const float* __restrict__ We, const float* __restrict__ W1,
                       const float* __restrict__ b1, const float* __restrict__ g1,
                       const float* __restrict__ bb1, const float* __restrict__ W2,
                       const float* __restrict__ b2, const float* __restrict__ g2,
                       const float* __restrict__ bb2)
{
    int i = blockIdx.x*blockDim.x + threadIdx.x;
    const float denom = (float)sqrt(1.0 + 1e-5);
    if (i < 768*Cc) {
        int o = i/Cc, c = i - o*Cc;
        d_WUV[i] = (o < 384) ? (We[o*384 + c] - We[o*384 + 192 + c])
                             : We[(o-384)*384 + 192 + c];
    }
    if (i < 256*384) {
        int o = i/384;
        d_W1s[i] = (o < 192) ? W1[i] * (g1[o]/denom) : 0.0f;
    }
    if (i < 256*192) {
        int o = i/192;
        d_W2s[i] = (o < 192) ? W2[i] * (g2[o]/denom) : 0.0f;
    }
    if (i < Cc) {
        d_c1[i] = b1[i]*(g1[i]/denom) + bb1[i];
        d_c2[i] = b2[i]*(g2[i]/denom) + bb2[i];
    }
}

// ---------------- xf = x + pos^T, normalize, sq ----------------
__global__ void prep_xf(const float* __restrict__ x, const float* __restrict__ pos)
{
    int j = blockIdx.x;               // node index 0..BNN-1
    int b = j / Nn, n = j - b*Nn;
    int c = threadIdx.x;              // 192 threads
    float v = x[((size_t)b*Cc + c)*Nn + n] + pos[n*Cc + c];
    d_xfT[(size_t)j*Cc + c] = v;

    __shared__ float red[Cc];
    __shared__ float s_nrm;
    red[c] = v*v;
    __syncthreads();
    if (c < 64) red[c] += red[c+64] + red[c+128];
    __syncthreads();
    if (c < 32) {
        float s = red[c] + red[c+32];
        #pragma unroll
        for (int o = 16; o; o >>= 1) s += __shfl_xor_sync(0xffffffffu, s, o);
        if (c == 0) s_nrm = fmaxf(sqrtf(s), 1e-12f);
    }
    __syncthreads();
    float xn = v / s_nrm;
    d_xnp[((size_t)b*NP + n)*Cc + c] = xn;

    red[c] = xn*xn;
    __syncthreads();
    if (c < 64) red[c] += red[c+64] + red[c+128];
    __syncthreads();
    if (c < 32) {
        float s = red[c] + red[c+32];
        #pragma unroll
        for (int o = 16; o; o >>= 1) s += __shfl_xor_sync(0xffffffffu, s, o);
        if (c == 0) d_sqp[b*NP + n] = s;
    }
}

// zero the pad rows of xnp; sentinel sq
__global__ void pad_fill()
{
    int r = blockIdx.x;               // 0 .. 8*96-1
    int b = r / (NP-Nn), pr = r - b*(NP-Nn);
    int row = Nn + pr;
    int c = threadIdx.x;
    d_xnp[((size_t)b*NP + row)*Cc + c] = 0.0f;
    if (c == 0) d_sqp[b*NP + row] = 1e30f;
}

// ---------------- symmetric dist GEMM (upper block pairs, mirrored write) ----------------
__global__ void __launch_bounds__(256) dist_sym()
{
    // decode pair index -> (by, bx) with bx >= by
    int p = blockIdx.x;
    int by = 0;
    while (p >= NBLK - by) { p -= NBLK - by; by++; }
    int bx = by + p;
    int z = blockIdx.z;

    const float* A = d_xnp + (size_t)z*NP*Cc;
    const float* sq = d_sqp + z*NP;
    float* dst = d_dist + (size_t)z*NP*NP;

    __shared__ __align__(16) float As[16][132];
    __shared__ __align__(16) float Bs[16][132];

    int tid  = threadIdx.x;
    int row0 = by*128, col0 = bx*128;
    int lr = tid >> 2;
    int lk = (tid & 3) << 2;
    int tx = tid & 15, ty = tid >> 4;

    float acc[8][8];
    #pragma unroll
    for (int i = 0; i < 8; i++)
        #pragma unroll
        for (int jj = 0; jj < 8; jj++) acc[i][jj] = 0.0f;

    for (int k0 = 0; k0 < Cc; k0 += 16) {
        #pragma unroll
        for (int rr = 0; rr < 2; rr++) {
            int r  = lr + rr*64;
            float4 va = *reinterpret_cast<const float4*>(&A[(size_t)(row0 + r)*Cc + k0 + lk]);
            As[lk+0][r]=va.x; As[lk+1][r]=va.y; As[lk+2][r]=va.z; As[lk+3][r]=va.w;
            float4 vb = *reinterpret_cast<const float4*>(&A[(size_t)(col0 + r)*Cc + k0 + lk]);
            Bs[lk+0][r]=vb.x; Bs[lk+1][r]=vb.y; Bs[lk+2][r]=vb.z; Bs[lk+3][r]=vb.w;
        }
        __syncthreads();
        #pragma unroll
        for (int kk = 0; kk < 16; kk++) {
            float a[8], b[8];
            *reinterpret_cast<float4*>(&a[0]) = *reinterpret_cast<const float4*>(&As[kk][ty*8]);
            *reinterpret_cast<float4*>(&a[4]) = *reinterpret_cast<const float4*>(&As[kk][ty*8+4]);
            *reinterpret_cast<float4*>(&b[0]) = *reinterpret_cast<const float4*>(&Bs[kk][tx*8]);
            *reinterpret_cast<float4*>(&b[4]) = *reinterpret_cast<const float4*>(&Bs[kk][tx*8+4]);
            #pragma unroll
            for (int i = 0; i < 8; i++)
                #pragma unroll
                for (int jj = 0; jj < 8; jj++)
                    acc[i][jj] = fmaf(a[i], b[jj], acc[i][jj]);
        }
        __syncthreads();
    }

    // upper write: dist[gr][gc] = (sq[gr] - 2a) + sq[gc]
    #pragma unroll
    for (int i = 0; i < 8; i++) {
        int gr = row0 + ty*8 + i;
        float sn = sq[gr];
        float o0[8];
        #pragma unroll
        for (int jj = 0; jj < 8; jj++)
            o0[jj] = (sn - 2.0f*acc[i][jj]) + sq[col0 + tx*8 + jj];
        float* d = &dst[(size_t)gr*NP + col0 + tx*8];
        *reinterpret_cast<float4*>(d)   = make_float4(o0[0],o0[1],o0[2],o0[3]);
        *reinterpret_cast<float4*>(d+4) = make_float4(o0[4],o0[5],o0[6],o0[7]);
    }

    // mirror write via smem transpose: dist[gc][gr] = (sq[gc] - 2a) + sq[gr]
    if (bx != by) {
        #pragma unroll 1
        for (int r8 = 0; r8 < 8; r8++) {
            __syncthreads();
            if ((tx >> 1) == r8) {
                #pragma unroll
                for (int i = 0; i < 8; i++)
                    #pragma unroll
                    for (int jj = 0; jj < 8; jj++)
                        As[(tx & 1)*8 + jj][ty*8 + i] = acc[i][jj];
            }
            __syncthreads();
            int row_l = tid >> 4;            // 0..15
            int col_l = (tid & 15) * 8;      // 0..120
            int gc = col0 + r8*16 + row_l;
            float sc = sq[gc];
            float o0[8];
            #pragma unroll
            for (int q = 0; q < 8; q++)
                o0[q] = (sc - 2.0f*As[row_l][col_l + q]) + sq[row0 + col_l + q];
            float* d = &dst[(size_t)gc*NP + row0 + col_l];
            *reinterpret_cast<float4*>(d)   = make_float4(o0[0],o0[1],o0[2],o0[3]);
            *reinterpret_cast<float4*>(d+4) = make_float4(o0[4],o0[5],o0[6],o0[7]);
        }
    }
}

// ---------------- NT GEMM template (modes 1..3) ----------------
// MODE 1: Yt = xf . WUV^T            (M=12544, N=768, K=192)
// MODE 2: h  = relu(g . W1s^T + c1)  (M=12544, N=192(pad256), K=384)
// MODE 3: out= relu(h . W2s^T + c2) + h, scattered to [B,C,N]
template<int MODE>
__global__ void __launch_bounds__(256) gemm_nt(float* __restrict__ outp)
{
    constexpr int KDIM = (MODE==2) ? 384 : 192;

    const float* A; const float* B;
    if (MODE==1)      { A = d_xfT; B = d_WUV; }
    else if (MODE==2) { A = d_gt;  B = d_W1s; }
    else              { A = d_ht;  B = d_W2s; }

    __shared__ __align__(16) float As[16][132];
    __shared__ __align__(16) float Bs[16][132];

    int tid  = threadIdx.x;
    int row0 = blockIdx.y*128, col0 = blockIdx.x*128;
    int lr = tid >> 2;
    int lk = (tid & 3) << 2;
    int tx = tid & 15, ty = tid >> 4;

    float acc[8][8];
    #pragma unroll
    for (int i = 0; i < 8; i++)
        #pragma unroll
        for (int jj = 0; jj < 8; jj++) acc[i][jj] = 0.0f;

    for (int k0 = 0; k0 < KDIM; k0 += 16) {
        #pragma unroll
        for (int rr = 0; rr < 2; rr++) {
            int r  = lr + rr*64;
            float4 va = *reinterpret_cast<const float4*>(&A[(size_t)(row0 + r)*KDIM + k0 + lk]);
            As[lk+0][r]=va.x; As[lk+1][r]=va.y; As[lk+2][r]=va.z; As[lk+3][r]=va.w;
            float4 vb = *reinterpret_cast<const float4*>(&B[(size_t)(col0 + r)*KDIM + k0 + lk]);
            Bs[lk+0][r]=vb.x; Bs[lk+1][r]=vb.y; Bs[lk+2][r]=vb.z; Bs[lk+3][r]=vb.w;
        }
        __syncthreads();
        #pragma unroll
        for (int kk = 0; kk < 16; kk++) {
            float a[8], b[8];
            *reinterpret_cast<float4*>(&a[0]) = *reinterpret_cast<const float4*>(&As[kk][ty*8]);
            *reinterpret_cast<float4*>(&a[4]) = *reinterpret_cast<const float4*>(&As[kk][ty*8+4]);
            *reinterpret_cast<float4*>(&b[0]) = *reinterpret_cast<const float4*>(&Bs[kk][tx*8]);
            *reinterpret_cast<float4*>(&b[4]) = *reinterpret_cast<const float4*>(&Bs[kk][tx*8+4]);
            #pragma unroll
            for (int i = 0; i < 8; i++)
                #pragma unroll
                for (int jj = 0; jj < 8; jj++)
                    acc[i][jj] = fmaf(a[i], b[jj], acc[i][jj]);
        }
        __syncthreads();
    }

    if (MODE == 1) {
        #pragma unroll
        for (int i = 0; i < 8; i++) {
            int gr = row0 + ty*8 + i;
            float* d = &d_Yt[(size_t)gr*768 + col0 + tx*8];
            *reinterpret_cast<float4*>(d)   = make_float4(acc[i][0],acc[i][1],acc[i][2],acc[i][3]);
            *reinterpret_cast<float4*>(d+4) = make_float4(acc[i][4],acc[i][5],acc[i][6],acc[i][7]);
        }
    } else if (MODE == 2) {
        #pragma unroll
        for (int i = 0; i < 8; i++) {
            int gr = row0 + ty*8 + i;
            #pragma unroll
            for (int jj = 0; jj < 8; jj++) {
                int gc = col0 + tx*8 + jj;
                if (gc < Cc)
                    d_ht[(size_t)gr*Cc + gc] = fmaxf(acc[i][jj] + d_c1[gc], 0.0f);
            }
        }
    } else {
        #pragma unroll
        for (int i = 0; i < 8; i++) {
            int gr = row0 + ty*8 + i;
            int b = gr / Nn, n = gr - b*Nn;
            #pragma unroll
            for (int jj = 0; jj < 8; jj++) {
                int gc = col0 + tx*8 + jj;
                if (gc < Cc)
                    outp[((size_t)b*Cc + gc)*Nn + n] =
                        fmaxf(acc[i][jj] + d_c2[gc], 0.0f) + d_ht[(size_t)gr*Cc + gc];
            }
        }
    }
}

// ---------------- top-9: threshold + candidate filter ----------------
__device__ __forceinline__ unsigned fkey32(float v) {
    unsigned u = __float_as_uint(v);
    return (u & 0x80000000u) ? ~u : (u | 0x80000000u);
}

#define TK_CAP 128

__global__ void __launch_bounds__(128) topk9()
{
    __shared__ unsigned long long kb_s[4][TK_CAP];
    int lane = threadIdx.x & 31;
    int w    = threadIdx.x >> 5;
    int row  = blockIdx.x*4 + w;
    if (row >= BNN) return;
    int b = row / Nn, n = row - b*Nn;
    const float* dr = d_dist + ((size_t)b*NP + n)*NP;
    unsigned long long* kb = kb_s[w];

    // pass 1: per-lane min over 13 float4 chunks (covers all 1664)
    float mv = FLT_MAX;
    #pragma unroll
    for (int i = 0; i < 13; i++) {
        float4 v = reinterpret_cast<const float4*>(dr)[i*32 + lane];
        mv = fminf(mv, fminf(fminf(v.x, v.y), fminf(v.z, v.w)));
    }

    // tau = 9th smallest of the 32 lane minima
    float tau = 0.0f;
    float mm = mv;
    #pragma unroll
    for (int r = 0; r < 9; r++) {
        float v = mm;
        #pragma unroll
        for (int off = 16; off; off >>= 1) v = fminf(v, __shfl_xor_sync(0xffffffffu, v, off));
        unsigned bl = __ballot_sync(0xffffffffu, mm == v);
        int src = __ffs(bl) - 1;
        if (lane == src) mm = FLT_MAX;
        tau = v;
    }

    // pass 2: compact candidates (v <= tau) into shared key buffer
    int cnt = 0;
    #pragma unroll 1
    for (int i = 0; i < 13; i++) {
        float4 v = reinterpret_cast<const float4*>(dr)[i*32 + lane];
        int mbase = (i*32 + lane)*4;
        float vv[4] = {v.x, v.y, v.z, v.w};
        #pragma unroll
        for (int c = 0; c < 4; c++) {
            bool pr = (vv[c] <= tau);
            unsigned msk = __ballot_sync(0xffffffffu, pr);
            if (pr) {
                int pos = cnt + __popc(msk & ((1u << lane) - 1u));
                if (pos < TK_CAP)
                    kb[pos] = ((unsigned long long)fkey32(vv[c]) << 32) | (unsigned)(mbase + c);
            }
            cnt += __popc(msk);
        }
    }

    if (cnt <= TK_CAP) {
        // 9 rounds of warp argmin over candidates (lex on (val,idx))
        #pragma unroll 1
        for (int r = 0; r < 9; r++) {
            unsigned long long best = ~0ULL;
            #pragma unroll
            for (int s = 0; s < 4; s++) {
                int pp = lane + s*32;
                if (pp < cnt) { unsigned long long k = kb[pp]; if (k < best) best = k; }
            }
            #pragma unroll
            for (int off = 16; off; off >>= 1) {
                unsigned long long o = __shfl_xor_sync(0xffffffffu, best, off);
                if (o < best) best = o;
            }
            #pragma unroll
            for (int s = 0; s < 4; s++) {
                int pp = lane + s*32;
                if (pp < cnt && kb[pp] == best) kb[pp] = ~0ULL;
            }
            if (lane == 0) d_nn[row*KK + r] = (int)(best & 0xffffffffu);
        }
    } else if (lane == 0) {
        // fallback: exact serial top-9 (practically never taken)
        unsigned long long bd[9];
        #pragma unroll
        for (int s = 0; s < 9; s++) bd[s] = ~0ULL;
        unsigned long long wk = ~0ULL; int ws = 0;
        for (int m = 0; m < NP; m++) {
            unsigned long long k = ((unsigned long long)fkey32(dr[m]) << 32) | (unsigned)m;
            if (k < wk) {
                bd[ws] = k;
                wk = bd[0]; ws = 0;
                #pragma unroll
                for (int s = 1; s < 9; s++) if (bd[s] > wk) { wk = bd[s]; ws = s; }
            }
        }
        #pragma unroll
        for (int s = 0; s < 9; s++) d_nn[row*KK + s] = (int)(bd[s] & 0xffffffffu);
    }
}

// ---------------- g = relu(U + be + max_k V[idx]) ----------------
__global__ void gather_max(const float* __restrict__ be)
{
    int j = blockIdx.x;
    int o = threadIdx.x;      // 384 threads
    int b = j / Nn;
    int base = b*Nn;
    int id[9];
    #pragma unroll
    for (int k = 0; k < 9; k++) id[k] = d_nn[j*9 + k];
    float m = -FLT_MAX;
    #pragma unroll
    for (int k = 0; k < 9; k++)
        m = fmaxf(m, d_Yt[(size_t)(base + id[k])*768 + 384 + o]);
    float u = d_Yt[(size_t)j*768 + o] + be[o];
    d_gt[(size_t)j*384 + o] = fmaxf(u + m, 0.0f);
}

// ---------------- launch ----------------
extern "C" void kernel_launch(void* const* d_in, const int* in_sizes, int n_in,
                              void* d_out, int out_size)
{
    const float* x   = (const float*)d_in[0];
    const float* pos = (const float*)d_in[1];
    const float* We  = (const float*)d_in[2];
    const float* be  = (const float*)d_in[3];
    const float* W1  = (const float*)d_in[4];
    const float* b1  = (const float*)d_in[5];
    const float* g1  = (const float*)d_in[6];
    const float* bb1 = (const float*)d_in[7];
    const float* W2  = (const float*)d_in[8];
    const float* b2  = (const float*)d_in[9];
    const float* g2  = (const float*)d_in[10];
    const float* bb2 = (const float*)d_in[11];
    float* out = (float*)d_out;

    prep_w<<<576, 256>>>(We, W1, b1, g1, bb1, W2, b2, g2, bb2);
    prep_xf<<<BNN, 192>>>(x, pos);
    pad_fill<<<Bz*(NP-Nn), 192>>>();
    { dim3 g(NBLK*(NBLK+1)/2, 1, Bz); dist_sym<<<g, 256>>>(); }   // 91 pairs x 8 batches
    topk9<<<(BNN+3)/4, 128>>>();
    { dim3 g(6, 98, 1);  gemm_nt<1><<<g, 256>>>(nullptr); }   // U,V
    gather_max<<<BNN, 384>>>(be);
    { dim3 g(2, 98, 1);  gemm_nt<2><<<g, 256>>>(nullptr); }   // h
    { dim3 g(2, 98, 1);  gemm_nt<3><<<g, 256>>>(out); }       // out
}

// round 5
// speedup vs baseline: 2.2313x; 1.3940x over previous
#include <cuda_runtime.h>
#include <cuda_bf16.h>
#include <math.h>
#include <float.h>

#define Bz 8
#define Cc 192
#define Nn 1568
#define NP 1664            /* 13*128 */
#define BNN (Bz*Nn)        /* 12544 = 98*128 */
#define KK 9

// smem tile geometry for the MMA GEMM
#define BK 32
#define TROW_B 80                /* bytes per smem row: 40 bf16 (32 + 8 pad) */
#define TILE_B (128*TROW_B)      /* 10240 bytes per operand tile */
#define STAGE_B (4*TILE_B)       /* Ah, Al, Bh, Bl */
#define GSMEM (2*STAGE_B)        /* 81920 bytes */

// ---------------- scratch (static device globals; no allocation) ----------------
__device__ __align__(256) __nv_bfloat16 d_xn_hi[(size_t)Bz*NP*Cc], d_xn_lo[(size_t)Bz*NP*Cc];
__device__ __align__(256) __nv_bfloat16 d_xf_hi[(size_t)BNN*Cc],   d_xf_lo[(size_t)BNN*Cc];
__device__ __align__(256) float d_sqp[Bz*NP];
__device__ __align__(256) float d_dist[(size_t)Bz*NP*NP];
__device__ __align__(256) int   d_nn[BNN*KK];
__device__ __align__(256) __nv_bfloat16 d_wuv_hi[768*Cc], d_wuv_lo[768*Cc];
__device__ __align__(256) __nv_bfloat16 d_w1_hi[256*384], d_w1_lo[256*384];
__device__ __align__(256) __nv_bfloat16 d_w2_hi[256*Cc],  d_w2_lo[256*Cc];
__device__ __align__(256) float d_c1[Cc], d_c2[Cc];
__device__ __align__(256) float d_Yt[(size_t)BNN*768];
__device__ __align__(256) __nv_bfloat16 d_g_hi[(size_t)BNN*384], d_g_lo[(size_t)BNN*384];
__device__ __align__(256) __nv_bfloat16 d_h_hi[(size_t)BNN*Cc],  d_h_lo[(size_t)BNN*Cc];
__device__ __align__(256) float d_htT[(size_t)Cc*BNN];     // shortcut, transposed [c][node]

// ---------------- PTX helpers ----------------
__device__ __forceinline__ unsigned smem_u32(const void* p) {
    unsigned a;
    asm("{ .reg .u64 t; cvta.to.shared.u64 t, %1; cvt.u32.u64 %0, t; }" : "=r"(a) : "l"(p));
    return a;
}
__device__ __forceinline__ void cpa16(unsigned s, const void* g) {
    asm volatile("cp.async.cg.shared.global [%0], [%1], 16;" :: "r"(s), "l"(g));
}
#define CP_COMMIT() asm volatile("cp.async.commit_group;" ::: "memory")
#define CP_WAIT(n)  asm volatile("cp.async.wait_group %0;" :: "n"(n) : "memory")

__device__ __forceinline__ void ldm4(unsigned* r, unsigned a) {
    asm volatile("ldmatrix.sync.aligned.m8n8.x4.shared.b16 {%0,%1,%2,%3}, [%4];"
        : "=r"(r[0]), "=r"(r[1]), "=r"(r[2]), "=r"(r[3]) : "r"(a));
}
__device__ __forceinline__ void mma_bf16(float* c, const unsigned* a, const unsigned* b) {
    asm volatile("mma.sync.aligned.m16n8k16.row.col.f32.bf16.bf16.f32 "
        "{%0,%1,%2,%3}, {%4,%5,%6,%7}, {%8,%9}, {%0,%1,%2,%3};"
        : "+f"(c[0]), "+f"(c[1]), "+f"(c[2]), "+f"(c[3])
        : "r"(a[0]), "r"(a[1]), "r"(a[2]), "r"(a[3]), "r"(b[0]), "r"(b[1]));
}

// ---------------- weight folding + bf16 split ----------------
__device__ __forceinline__ void split_store(float v, __nv_bfloat16* hi, __nv_bfloat16* lo, size_t i) {
    __nv_bfloat16 h = __float2bfloat16(v);
    hi[i] = h;
    lo[i] = __float2bfloat16(v - __bfloat162float(h));
}

__global__ void prep_w(const float* __restrict__ We, const float* __restrict__ W1,
                       const float* __restrict__ b1, const float* __restrict__ g1,
                       const float* __restrict__ bb1, const float* __restrict__ W2,
                       const float* __restrict__ b2, const float* __restrict__ g2,
                       const float* __restrict__ bb2)
{
    int i = blockIdx.x*blockDim.x + threadIdx.x;
    const float denom = (float)sqrt(1.0 + 1e-5);
    if (i < 768*Cc) {
        int o = i/Cc, c = i - o*Cc;
        float v = (o < 384) ? (We[o*384 + c] - We[o*384 + 192 + c])
                            : We[(o-384)*384 + 192 + c];
        split_store(v, d_wuv_hi, d_wuv_lo, i);
    }
    if (i < 256*384) {
        int o = i/384;
        float v = (o < 192) ? W1[i] * (g1[o]/denom) : 0.0f;
        split_store(v, d_w1_hi, d_w1_lo, i);
    }
    if (i < 256*192) {
        int o = i/192;
        float v = (o < 192) ? W2[i] * (g2[o]/denom) : 0.0f;
        split_store(v, d_w2_hi, d_w2_lo, i);
    }
    if (i < Cc) {
        d_c1[i] = b1[i]*(g1[i]/denom) + bb1[i];
        d_c2[i] = b2[i]*(g2[i]/denom) + bb2[i];
    }
}

// ---------------- xf = x + pos^T, normalize, sq; bf16 splits ----------------
__global__ void prep_xf(const float* __restrict__ x, const float* __restrict__ pos)
{
    int j = blockIdx.x;
    int b = j / Nn, n = j - b*Nn;
    int c = threadIdx.x;              // 192 threads
    float v = x[((size_t)b*Cc + c)*Nn + n] + pos[n*Cc + c];
    split_store(v, d_xf_hi, d_xf_lo, (size_t)j*Cc + c);

    __shared__ float red[Cc];
    __shared__ float s_nrm;
    red[c] = v*v;
    __syncthreads();
    if (c < 64) red[c] += red[c+64] + red[c+128];
    __syncthreads();
    if (c < 32) {
        float s = red[c] + red[c+32];
        #pragma unroll
        for (int o = 16; o; o >>= 1) s += __shfl_xor_sync(0xffffffffu, s, o);
        if (c == 0) s_nrm = fmaxf(sqrtf(s), 1e-12f);
    }
    __syncthreads();
    float xn = v / s_nrm;
    split_store(xn, d_xn_hi, d_xn_lo, ((size_t)b*NP + n)*Cc + c);

    red[c] = xn*xn;
    __syncthreads();
    if (c < 64) red[c] += red[c+64] + red[c+128];
    __syncthreads();
    if (c < 32) {
        float s = red[c] + red[c+32];
        #pragma unroll
        for (int o = 16; o; o >>= 1) s += __shfl_xor_sync(0xffffffffu, s, o);
        if (c == 0) d_sqp[b*NP + n] = s;
    }
}

__global__ void pad_fill()
{
    int r = blockIdx.x;               // 0..8*96-1
    int b = r / (NP-Nn), pr = r - b*(NP-Nn);
    int row = Nn + pr;
    int c = threadIdx.x;
    size_t i = ((size_t)b*NP + row)*Cc + c;
    d_xn_hi[i] = __float2bfloat16(0.0f);
    d_xn_lo[i] = __float2bfloat16(0.0f);
    if (c == 0) d_sqp[b*NP + row] = 1e30f;
}

// ---------------- warp-MMA GEMM, 128x128 tile, split bf16 (hh + hl + lh) ----------------
// MODE 0: dist (per-batch xn . xn^T + sq epilogue)   grid (13,13,8), K=192
// MODE 1: Yt = xf . WUV^T                            grid (6,98),   K=192
// MODE 2: h  = relu(g . W1s^T + c1) -> split + htT   grid (2,98),   K=384
// MODE 3: out = relu(h . W2s^T + c2) + htT, scatter  grid (2,98),   K=192
template<int MODE>
__global__ void __launch_bounds__(256, 1) mma_gemm(float* __restrict__ outp)
{
    constexpr int KDIM = (MODE == 2) ? 384 : 192;
    constexpr int NCH  = KDIM / BK;

    extern __shared__ char sm[];
    unsigned sb = smem_u32(sm);
    int tid = threadIdx.x, lane = tid & 31, wid = tid >> 5;
    int warp_m = wid & 1, warp_n = wid >> 1;          // 2 x 4
    int bx = blockIdx.x, by = blockIdx.y, z = blockIdx.z;
    int row0 = by*128, col0 = bx*128;

    const __nv_bfloat16 *Ah, *Al, *Bh, *Bl;
    if (MODE == 0) {
        size_t zo = (size_t)z*NP*Cc;
        Ah = d_xn_hi + zo; Al = d_xn_lo + zo; Bh = Ah; Bl = Al;
    } else if (MODE == 1) {
        Ah = d_xf_hi; Al = d_xf_lo; Bh = d_wuv_hi; Bl = d_wuv_lo;
    } else if (MODE == 2) {
        Ah = d_g_hi;  Al = d_g_lo;  Bh = d_w1_hi;  Bl = d_w1_lo;
    } else {
        Ah = d_h_hi;  Al = d_h_lo;  Bh = d_w2_hi;  Bl = d_w2_lo;
    }
    const __nv_bfloat16* srcs[4] = {Ah, Al, Bh, Bl};
    int rbase[4] = {row0, row0, col0, col0};

    float acc[4][4][4];
    #pragma unroll
    for (int mt = 0; mt < 4; mt++)
        #pragma unroll
        for (int nt = 0; nt < 4; nt++)
            #pragma unroll
            for (int e = 0; e < 4; e++) acc[mt][nt][e] = 0.0f;

    // ---- async loader for one k-chunk into stage s ----
    auto load_chunk = [&](int ch, int s) {
        unsigned so = sb + s*STAGE_B;
        int k0 = ch*BK;
        #pragma unroll
        for (int t = 0; t < 4; t++) {
            #pragma unroll
            for (int q = 0; q < 2; q++) {
                int v = tid + q*256;            // 0..511
                int row = v >> 2, c4 = v & 3;
                cpa16(so + t*TILE_B + row*TROW_B + c4*16,
                      srcs[t] + (size_t)(rbase[t] + row)*KDIM + k0 + c4*8);
            }
        }
    };

    load_chunk(0, 0);
    CP_COMMIT();

    for (int ch = 0; ch < NCH; ch++) {
        if (ch + 1 < NCH) { load_chunk(ch+1, (ch+1)&1); CP_COMMIT(); CP_WAIT(1); }
        else              { CP_WAIT(0); }
        __syncthreads();

        unsigned so = sb + (ch&1)*STAGE_B;
        #pragma unroll
        for (int ks = 0; ks < 2; ks++) {
            unsigned ah[4][4], al[4][4], bh[4][2], bl[4][2];
            #pragma unroll
            for (int mt = 0; mt < 4; mt++) {
                unsigned ra = so + (warp_m*64 + mt*16 + (lane & 15))*TROW_B
                            + ks*32 + (lane >> 4)*16;
                ldm4(ah[mt], ra);
                ldm4(al[mt], ra + TILE_B);
            }
            #pragma unroll
            for (int p = 0; p < 2; p++) {
                int nrow = warp_n*32 + p*16 + (lane >> 4)*8 + (lane & 7);
                unsigned rb = so + 2*TILE_B + nrow*TROW_B + ks*32 + ((lane >> 3) & 1)*16;
                unsigned r4[4];
                ldm4(r4, rb);
                bh[2*p][0] = r4[0]; bh[2*p][1] = r4[1];
                bh[2*p+1][0] = r4[2]; bh[2*p+1][1] = r4[3];
                ldm4(r4, rb + TILE_B);
                bl[2*p][0] = r4[0]; bl[2*p][1] = r4[1];
                bl[2*p+1][0] = r4[2]; bl[2*p+1][1] = r4[3];
            }
            #pragma unroll
            for (int mt = 0; mt < 4; mt++)
                #pragma unroll
                for (int nt = 0; nt < 4; nt++) {
                    mma_bf16(acc[mt][nt], ah[mt], bh[nt]);
                    mma_bf16(acc[mt][nt], ah[mt], bl[nt]);
                    mma_bf16(acc[mt][nt], al[mt], bh[nt]);
                }
        }
        __syncthreads();
    }

    // ---------------- epilogue: 4 groups of 32 cols, staged through smem ----------------
    float* stage = reinterpret_cast<float*>(sm);   // 128 x 33 floats (16.9 KB)

    #pragma unroll 1
    for (int g = 0; g < 4; g++) {
        int cb = g*32;
        if (warp_n == g) {
            #pragma unroll
            for (int mt = 0; mt < 4; mt++) {
                int r0 = warp_m*64 + mt*16 + (lane >> 2);
                float s0 = 0.0f, s8 = 0.0f;
                if (MODE == 0) {
                    s0 = d_sqp[z*NP + row0 + r0];
                    s8 = d_sqp[z*NP + row0 + r0 + 8];
                }
                #pragma unroll
                for (int nt = 0; nt < 4; nt++) {
                    int c0 = nt*8 + (lane & 3)*2;
                    float v0 = acc[mt][nt][0], v1 = acc[mt][nt][1];
                    float v2 = acc[mt][nt][2], v3 = acc[mt][nt][3];
                    if (MODE == 0) {
                        v0 = s0 - 2.0f*v0; v1 = s0 - 2.0f*v1;
                        v2 = s8 - 2.0f*v2; v3 = s8 - 2.0f*v3;
                    }
                    stage[r0*33 + c0]     = v0; stage[r0*33 + c0 + 1]     = v1;
                    stage[(r0+8)*33 + c0] = v2; stage[(r0+8)*33 + c0 + 1] = v3;
                }
            }
        }
        __syncthreads();

        if (MODE == 0) {
            float sqc = d_sqp[z*NP + col0 + cb + lane];
            float* dst = d_dist + (size_t)z*NP*NP;
            #pragma unroll 4
            for (int rr = 0; rr < 16; rr++) {
                int r = wid*16 + rr;
                dst[(size_t)(row0 + r)*NP + col0 + cb + lane] = stage[r*33 + lane] + sqc;
            }
        } else if (MODE == 1) {
            #pragma unroll 4
            for (int rr = 0; rr < 16; rr++) {
                int r = wid*16 + rr;
                d_Yt[(size_t)(row0 + r)*768 + col0 + cb + lane] = stage[r*33 + lane];
            }
        } else if (MODE == 2) {
            int gc = col0 + cb + lane;
            if (gc < Cc) {
                float c1v = d_c1[gc];
                #pragma unroll 4
                for (int rr = 0; rr < 16; rr++) {
                    int r = wid*16 + rr;
                    float v = fmaxf(stage[r*33 + lane] + c1v, 0.0f);
                    split_store(v, d_h_hi, d_h_lo, (size_t)(row0 + r)*Cc + gc);
                }
            }
            #pragma unroll
            for (int q = 0; q < 4; q++) {
                int cc = wid*4 + q;
                int gcb = col0 + cb + cc;
                if (gcb < Cc) {
                    float c1v = d_c1[gcb];
                    #pragma unroll
                    for (int it = 0; it < 4; it++) {
                        int r = it*32 + lane;
                        float v = fmaxf(stage[r*33 + cc] + c1v, 0.0f);
                        d_htT[(size_t)gcb*BNN + row0 + r] = v;
                    }
                }
            }
        } else {
            #pragma unroll
            for (int q = 0; q < 4; q++) {
                int cc = wid*4 + q;
                int gc = col0 + cb + cc;
                if (gc < Cc) {
                    float c2v = d_c2[gc];
                    #pragma unroll
                    for (int it = 0; it < 4; it++) {
                        int r = it*32 + lane;
                        int gr = row0 + r;
                        float v = fmaxf(stage[r*33 + cc] + c2v, 0.0f)
                                + d_htT[(size_t)gc*BNN + gr];
                        int b = gr / Nn, n = gr - b*Nn;
                        outp[((size_t)b*Cc + gc)*Nn + n] = v;
                    }
                }
            }
        }
        __syncthreads();
    }
}

// ---------------- top-9: threshold + candidate filter ----------------
__device__ __forceinline__ unsigned fkey32(float v) {
    unsigned u = __float_as_uint(v);
    return (u & 0x80000000u) ? ~u : (u | 0x80000000u);
}

#define TK_CAP 128

__global__ void __launch_bounds__(128) topk9()
{
    __shared__ unsigned long long kb_s[4][TK_CAP];
    int lane = threadIdx.x & 31;
    int w    = threadIdx.x >> 5;
    int row  = blockIdx.x*4 + w;
    if (row >= BNN) return;
    int b = row / Nn, n = row - b*Nn;
    const float* dr = d_dist + ((size_t)b*NP + n)*NP;
    unsigned long long* kb = kb_s[w];

    float mv = FLT_MAX;
    #pragma unroll
    for (int i = 0; i < 13; i++) {
        float4 v = reinterpret_cast<const float4*>(dr)[i*32 + lane];
        mv = fminf(mv, fminf(fminf(v.x, v.y), fminf(v.z, v.w)));
    }

    float tau = 0.0f;
    float mm = mv;
    #pragma unroll
    for (int r = 0; r < 9; r++) {
        float v = mm;
        #pragma unroll
        for (int off = 16; off; off >>= 1) v = fminf(v, __shfl_xor_sync(0xffffffffu, v, off));
        unsigned bl = __ballot_sync(0xffffffffu, mm == v);
        int src = __ffs(bl) - 1;
        if (lane == src) mm = FLT_MAX;
        tau = v;
    }

    int cnt = 0;
    #pragma unroll 1
    for (int i = 0; i < 13; i++) {
        float4 v = reinterpret_cast<const float4*>(dr)[i*32 + lane];
        int mbase = (i*32 + lane)*4;
        float vv[4] = {v.x, v.y, v.z, v.w};
        #pragma unroll
        for (int c = 0; c < 4; c++) {
            bool pr = (vv[c] <= tau);
            unsigned msk = __ballot_sync(0xffffffffu, pr);
            if (pr) {
                int pos = cnt + __popc(msk & ((1u << lane) - 1u));
                if (pos < TK_CAP)
                    kb[pos] = ((unsigned long long)fkey32(vv[c]) << 32) | (unsigned)(mbase + c);
            }
            cnt += __popc(msk);
        }
    }

    if (cnt <= TK_CAP) {
        #pragma unroll 1
        for (int r = 0; r < 9; r++) {
            unsigned long long best = ~0ULL;
            #pragma unroll
            for (int s = 0; s < 4; s++) {
                int pp = lane + s*32;
                if (pp < cnt) { unsigned long long k = kb[pp]; if (k < best) best = k; }
            }
            #pragma unroll
            for (int off = 16; off; off >>= 1) {
                unsigned long long o = __shfl_xor_sync(0xffffffffu, best, off);
                if (o < best) best = o;
            }
            #pragma unroll
            for (int s = 0; s < 4; s++) {
                int pp = lane + s*32;
                if (pp < cnt && kb[pp] == best) kb[pp] = ~0ULL;
            }
            if (lane == 0) d_nn[row*KK + r] = (int)(best & 0xffffffffu);
        }
    } else if (lane == 0) {
        unsigned long long bd[9];
        #pragma unroll
        for (int s = 0; s < 9; s++) bd[s] = ~0ULL;
        unsigned long long wk = ~0ULL; int ws = 0;
        for (int m2 = 0; m2 < NP; m2++) {
            unsigned long long k = ((unsigned long long)fkey32(dr[m2]) << 32) | (unsigned)m2;
            if (k < wk) {
                bd[ws] = k;
                wk = bd[0]; ws = 0;
                #pragma unroll
                for (int s = 1; s < 9; s++) if (bd[s] > wk) { wk = bd[s]; ws = s; }
            }
        }
        #pragma unroll
        for (int s = 0; s < 9; s++) d_nn[row*KK + s] = (int)(bd[s] & 0xffffffffu);
    }
}

// ---------------- g = relu(U + be + max_k V[idx]); emit bf16 split ----------------
__global__ void gather_max(const float* __restrict__ be)
{
    int j = blockIdx.x;
    int o = threadIdx.x;      // 384 threads
    int b = j / Nn;
    int base = b*Nn;
    int id[9];
    #pragma unroll
    for (int k = 0; k < 9; k++) id[k] = d_nn[j*9 + k];
    float m = -FLT_MAX;
    #pragma unroll
    for (int k = 0; k < 9; k++)
        m = fmaxf(m, d_Yt[(size_t)(base + id[k])*768 + 384 + o]);
    float u = d_Yt[(size_t)j*768 + o] + be[o];
    float v = fmaxf(u + m, 0.0f);
    split_store(v, d_g_hi, d_g_lo, (size_t)j*384 + o);
}

// ---------------- launch ----------------
extern "C" void kernel_launch(void* const* d_in, const int* in_sizes, int n_in,
                              void* d_out, int out_size)
{
    const float* x   = (const float*)d_in[0];
    const float* pos = (const float*)d_in[1];
    const float* We  = (const float*)d_in[2];
    const float* be  = (const float*)d_in[3];
    const float* W1  = (const float*)d_in[4];
    const float* b1  = (const float*)d_in[5];
    const float* g1  = (const float*)d_in[6];
    const float* bb1 = (const float*)d_in[7];
    const float* W2  = (const float*)d_in[8];
    const float* b2  = (const float*)d_in[9];
    const float* g2  = (const float*)d_in[10];
    const float* bb2 = (const float*)d_in[11];
    float* out = (float*)d_out;

    cudaFuncSetAttribute(mma_gemm<0>, cudaFuncAttributeMaxDynamicSharedMemorySize, GSMEM);
    cudaFuncSetAttribute(mma_gemm<1>, cudaFuncAttributeMaxDynamicSharedMemorySize, GSMEM);
    cudaFuncSetAttribute(mma_gemm<2>, cudaFuncAttributeMaxDynamicSharedMemorySize, GSMEM);
    cudaFuncSetAttribute(mma_gemm<3>, cudaFuncAttributeMaxDynamicSharedMemorySize, GSMEM);

    prep_w<<<576, 256>>>(We, W1, b1, g1, bb1, W2, b2, g2, bb2);
    prep_xf<<<BNN, 192>>>(x, pos);
    pad_fill<<<Bz*(NP-Nn), 192>>>();
    { dim3 g(13, 13, 8); mma_gemm<0><<<g, 256, GSMEM>>>(nullptr); }
    topk9<<<(BNN+3)/4, 128>>>();
    { dim3 g(6, 98, 1);  mma_gemm<1><<<g, 256, GSMEM>>>(nullptr); }
    gather_max<<<BNN, 384>>>(be);
    { dim3 g(2, 98, 1);  mma_gemm<2><<<g, 256, GSMEM>>>(nullptr); }
    { dim3 g(2, 98, 1);  mma_gemm<3><<<g, 256, GSMEM>>>(out); }
}

// round 6
// speedup vs baseline: 3.1447x; 1.4094x over previous
#include <cuda_runtime.h>
#include <cuda_bf16.h>
#include <math.h>
#include <float.h>

#define Bz 8
#define Cc 192
#define Nn 1568
#define NP 1664            /* 13*128 */
#define BNN (Bz*Nn)        /* 12544 = 98*128 */
#define KK 9
#define NBLK 13

// smem tile geometry for the MMA GEMM
#define BK 32
#define TROW_B 80                /* bytes per smem row: 40 bf16 (32 + 8 pad) */
#define TILE_B (128*TROW_B)      /* 10240 bytes per operand tile */
#define STAGE_B (4*TILE_B)       /* Ah, Al, Bh, Bl */
#define GSMEM (2*STAGE_B)        /* 81920 bytes */

// ---------------- scratch (static device globals; no allocation) ----------------
__device__ __align__(256) __nv_bfloat16 d_xn_hi[(size_t)Bz*NP*Cc], d_xn_lo[(size_t)Bz*NP*Cc];
__device__ __align__(256) __nv_bfloat16 d_xf_hi[(size_t)BNN*Cc],   d_xf_lo[(size_t)BNN*Cc];
__device__ __align__(256) float d_sqp[Bz*NP];
__device__ __align__(256) float d_dist[(size_t)Bz*NP*NP];
__device__ __align__(256) int   d_nn[BNN*KK];
__device__ __align__(256) __nv_bfloat16 d_wuv_hi[768*Cc], d_wuv_lo[768*Cc];
__device__ __align__(256) __nv_bfloat16 d_w1_hi[256*384], d_w1_lo[256*384];
__device__ __align__(256) __nv_bfloat16 d_w2_hi[256*Cc],  d_w2_lo[256*Cc];
__device__ __align__(256) float d_c1[Cc], d_c2[Cc];
__device__ __align__(256) float d_Yt[(size_t)BNN*768];
__device__ __align__(256) __nv_bfloat16 d_g_hi[(size_t)BNN*384], d_g_lo[(size_t)BNN*384];
__device__ __align__(256) __nv_bfloat16 d_h_hi[(size_t)BNN*Cc],  d_h_lo[(size_t)BNN*Cc];
__device__ __align__(256) float d_htT[(size_t)Cc*BNN];     // shortcut, transposed [c][node]

// ---------------- PTX helpers ----------------
__device__ __forceinline__ unsigned smem_u32(const void* p) {
    unsigned a;
    asm("{ .reg .u64 t; cvta.to.shared.u64 t, %1; cvt.u32.u64 %0, t; }" : "=r"(a) : "l"(p));
    return a;
}
__device__ __forceinline__ void cpa16(unsigned s, const void* g) {
    asm volatile("cp.async.cg.shared.global [%0], [%1], 16;" :: "r"(s), "l"(g));
}
#define CP_COMMIT() asm volatile("cp.async.commit_group;" ::: "memory")
#define CP_WAIT(n)  asm volatile("cp.async.wait_group %0;" :: "n"(n) : "memory")

__device__ __forceinline__ void ldm4(unsigned* r, unsigned a) {
    asm volatile("ldmatrix.sync.aligned.m8n8.x4.shared.b16 {%0,%1,%2,%3}, [%4];"
        : "=r"(r[0]), "=r"(r[1]), "=r"(r[2]), "=r"(r[3]) : "r"(a));
}
__device__ __forceinline__ void mma_bf16(float* c, const unsigned* a, const unsigned* b) {
    asm volatile("mma.sync.aligned.m16n8k16.row.col.f32.bf16.bf16.f32 "
        "{%0,%1,%2,%3}, {%4,%5,%6,%7}, {%8,%9}, {%0,%1,%2,%3};"
        : "+f"(c[0]), "+f"(c[1]), "+f"(c[2]), "+f"(c[3])
        : "r"(a[0]), "r"(a[1]), "r"(a[2]), "r"(a[3]), "r"(b[0]), "r"(b[1]));
}

// ---------------- weight folding + bf16 split ----------------
__device__ __forceinline__ void split_store(float v, __nv_bfloat16* hi, __nv_bfloat16* lo, size_t i) {
    __nv_bfloat16 h = __float2bfloat16(v);
    hi[i] = h;
    lo[i] = __float2bfloat16(v - __bfloat162float(h));
}

__global__ void prep_w(const float* __restrict__ We, const float* __restrict__ W1,
                       const float* __restrict__ b1, const float* __restrict__ g1,
                       const float* __restrict__ bb1, const float* __restrict__ W2,
                       const float* __restrict__ b2, const float* __restrict__ g2,
                       const float* __restrict__ bb2)
{
    int i = blockIdx.x*blockDim.x + threadIdx.x;
    const float denom = (float)sqrt(1.0 + 1e-5);
    if (i < 768*Cc) {
        int o = i/Cc, c = i - o*Cc;
        float v = (o < 384) ? (We[o*384 + c] - We[o*384 + 192 + c])
                            : We[(o-384)*384 + 192 + c];
        split_store(v, d_wuv_hi, d_wuv_lo, i);
    }
    if (i < 256*384) {
        int o = i/384;
        float v = (o < 192) ? W1[i] * (g1[o]/denom) : 0.0f;
        split_store(v, d_w1_hi, d_w1_lo, i);
    }
    if (i < 256*192) {
        int o = i/192;
        float v = (o < 192) ? W2[i] * (g2[o]/denom) : 0.0f;
        split_store(v, d_w2_hi, d_w2_lo, i);
    }
    if (i < Cc) {
        d_c1[i] = b1[i]*(g1[i]/denom) + bb1[i];
        d_c2[i] = b2[i]*(g2[i]/denom) + bb2[i];
    }
}

// ---------------- xf = x + pos^T, normalize, sq; bf16 splits ----------------
__global__ void prep_xf(const float* __restrict__ x, const float* __restrict__ pos)
{
    int j = blockIdx.x;
    int b = j / Nn, n = j - b*Nn;
    int c = threadIdx.x;              // 192 threads
    float v = x[((size_t)b*Cc + c)*Nn + n] + pos[n*Cc + c];
    split_store(v, d_xf_hi, d_xf_lo, (size_t)j*Cc + c);

    __shared__ float red[Cc];
    __shared__ float s_nrm;
    red[c] = v*v;
    __syncthreads();
    if (c < 64) red[c] += red[c+64] + red[c+128];
    __syncthreads();
    if (c < 32) {
        float s = red[c] + red[c+32];
        #pragma unroll
        for (int o = 16; o; o >>= 1) s += __shfl_xor_sync(0xffffffffu, s, o);
        if (c == 0) s_nrm = fmaxf(sqrtf(s), 1e-12f);
    }
    __syncthreads();
    float xn = v / s_nrm;
    split_store(xn, d_xn_hi, d_xn_lo, ((size_t)b*NP + n)*Cc + c);

    red[c] = xn*xn;
    __syncthreads();
    if (c < 64) red[c] += red[c+64] + red[c+128];
    __syncthreads();
    if (c < 32) {
        float s = red[c] + red[c+32];
        #pragma unroll
        for (int o = 16; o; o >>= 1) s += __shfl_xor_sync(0xffffffffu, s, o);
        if (c == 0) d_sqp[b*NP + n] = s;
    }
}

__global__ void pad_fill()
{
    int r = blockIdx.x;               // 0..8*96-1
    int b = r / (NP-Nn), pr = r - b*(NP-Nn);
    int row = Nn + pr;
    int c = threadIdx.x;
    size_t i = ((size_t)b*NP + row)*Cc + c;
    d_xn_hi[i] = __float2bfloat16(0.0f);
    d_xn_lo[i] = __float2bfloat16(0.0f);
    if (c == 0) d_sqp[b*NP + row] = 1e30f;
}

// ============ shared mainloop: computes 128x128 accs from Ah/Al vs Bh/Bl ============
template<int KDIM>
__device__ __forceinline__ void mma_mainloop(
    const __nv_bfloat16* const* srcs, const int* rbase,
    unsigned sb, int tid, int lane, int warp_m, int warp_n,
    float acc[4][4][4])
{
    constexpr int NCH = KDIM / BK;
    auto load_chunk = [&](int ch, int s) {
        unsigned so = sb + s*STAGE_B;
        int k0 = ch*BK;
        #pragma unroll
        for (int t = 0; t < 4; t++) {
            #pragma unroll
            for (int q = 0; q < 2; q++) {
                int v = tid + q*256;
                int row = v >> 2, c4 = v & 3;
                cpa16(so + t*TILE_B + row*TROW_B + c4*16,
                      srcs[t] + (size_t)(rbase[t] + row)*KDIM + k0 + c4*8);
            }
        }
    };

    load_chunk(0, 0);
    CP_COMMIT();

    for (int ch = 0; ch < NCH; ch++) {
        if (ch + 1 < NCH) { load_chunk(ch+1, (ch+1)&1); CP_COMMIT(); CP_WAIT(1); }
        else              { CP_WAIT(0); }
        __syncthreads();

        unsigned so = sb + (ch&1)*STAGE_B;
        #pragma unroll
        for (int ks = 0; ks < 2; ks++) {
            unsigned ah[4][4], al[4][4], bh[4][2], bl[4][2];
            #pragma unroll
            for (int mt = 0; mt < 4; mt++) {
                unsigned ra = so + (warp_m*64 + mt*16 + (lane & 15))*TROW_B
                            + ks*32 + (lane >> 4)*16;
                ldm4(ah[mt], ra);
                ldm4(al[mt], ra + TILE_B);
            }
            #pragma unroll
            for (int p = 0; p < 2; p++) {
                int nrow = warp_n*32 + p*16 + (lane >> 4)*8 + (lane & 7);
                unsigned rb = so + 2*TILE_B + nrow*TROW_B + ks*32 + ((lane >> 3) & 1)*16;
                unsigned r4[4];
                ldm4(r4, rb);
                bh[2*p][0] = r4[0]; bh[2*p][1] = r4[1];
                bh[2*p+1][0] = r4[2]; bh[2*p+1][1] = r4[3];
                ldm4(r4, rb + TILE_B);
                bl[2*p][0] = r4[0]; bl[2*p][1] = r4[1];
                bl[2*p+1][0] = r4[2]; bl[2*p+1][1] = r4[3];
            }
            #pragma unroll
            for (int mt = 0; mt < 4; mt++)
                #pragma unroll
                for (int nt = 0; nt < 4; nt++) {
                    mma_bf16(acc[mt][nt], ah[mt], bh[nt]);
                    mma_bf16(acc[mt][nt], ah[mt], bl[nt]);
                    mma_bf16(acc[mt][nt], al[mt], bh[nt]);
                }
        }
        __syncthreads();
    }
}

// ---------------- dist GEMM: symmetric, upper block pairs, mirror write ----------------
__global__ void __launch_bounds__(256, 2) mma_dist()
{
    extern __shared__ char sm[];
    unsigned sb = smem_u32(sm);
    int tid = threadIdx.x, lane = tid & 31, wid = tid >> 5;
    int warp_m = wid & 1, warp_n = wid >> 1;
    int z = blockIdx.z;

    // decode pair -> (by, bx), bx >= by
    int p = blockIdx.x, by = 0;
    while (p >= NBLK - by) { p -= NBLK - by; by++; }
    int bx = by + p;
    int row0 = by*128, col0 = bx*128;

    size_t zo = (size_t)z*NP*Cc;
    const __nv_bfloat16* srcs[4] = {d_xn_hi + zo, d_xn_lo + zo, d_xn_hi + zo, d_xn_lo + zo};
    int rbase[4] = {row0, row0, col0, col0};

    float acc[4][4][4];
    #pragma unroll
    for (int mt = 0; mt < 4; mt++)
        #pragma unroll
        for (int nt = 0; nt < 4; nt++)
            #pragma unroll
            for (int e = 0; e < 4; e++) acc[mt][nt][e] = 0.0f;

    mma_mainloop<Cc>(srcs, rbase, sb, tid, lane, warp_m, warp_n, acc);

    float* stage = reinterpret_cast<float*>(sm);   // 128 x 33 floats
    const float* sq = d_sqp + z*NP;
    float* dst = d_dist + (size_t)z*NP*NP;
    bool mirror = (bx != by);

    #pragma unroll 1
    for (int g = 0; g < 4; g++) {
        int cb = g*32;
        if (warp_n == g) {
            #pragma unroll
            for (int mt = 0; mt < 4; mt++) {
                int r0 = warp_m*64 + mt*16 + (lane >> 2);
                float s0 = sq[row0 + r0];
                float s8 = sq[row0 + r0 + 8];
                #pragma unroll
                for (int nt = 0; nt < 4; nt++) {
                    int c0 = nt*8 + (lane & 3)*2;
                    stage[r0*33 + c0]     = s0 - 2.0f*acc[mt][nt][0];
                    stage[r0*33 + c0 + 1] = s0 - 2.0f*acc[mt][nt][1];
                    stage[(r0+8)*33 + c0]     = s8 - 2.0f*acc[mt][nt][2];
                    stage[(r0+8)*33 + c0 + 1] = s8 - 2.0f*acc[mt][nt][3];
                }
            }
        }
        __syncthreads();

        // upper write (row-major)
        {
            float sqc = sq[col0 + cb + lane];
            #pragma unroll 4
            for (int rr = 0; rr < 16; rr++) {
                int r = wid*16 + rr;
                dst[(size_t)(row0 + r)*NP + col0 + cb + lane] = stage[r*33 + lane] + sqc;
            }
        }
        // mirror write (transposed, coalesced along rows)
        if (mirror) {
            #pragma unroll
            for (int q = 0; q < 4; q++) {
                int cc = wid*4 + q;
                float sqc = sq[col0 + cb + cc];
                #pragma unroll
                for (int it = 0; it < 4; it++) {
                    int r = it*32 + lane;
                    dst[(size_t)(col0 + cb + cc)*NP + row0 + r] = stage[r*33 + cc] + sqc;
                }
            }
        }
        __syncthreads();
    }
}

// ---------------- general GEMMs (modes 1..3) ----------------
// MODE 1: Yt = xf . WUV^T                            grid (6,98),   K=192
// MODE 2: h  = relu(g . W1s^T + c1) -> split + htT   grid (2,98),   K=384
// MODE 3: out = relu(h . W2s^T + c2) + htT, scatter  grid (2,98),   K=192
template<int MODE>
__global__ void __launch_bounds__(256, 2) mma_gemm(float* __restrict__ outp)
{
    constexpr int KDIM = (MODE == 2) ? 384 : 192;

    extern __shared__ char sm[];
    unsigned sb = smem_u32(sm);
    int tid = threadIdx.x, lane = tid & 31, wid = tid >> 5;
    int warp_m = wid & 1, warp_n = wid >> 1;
    int bx = blockIdx.x, by = blockIdx.y;
    int row0 = by*128, col0 = bx*128;

    const __nv_bfloat16 *Ah, *Al, *Bh, *Bl;
    if (MODE == 1)      { Ah = d_xf_hi; Al = d_xf_lo; Bh = d_wuv_hi; Bl = d_wuv_lo; }
    else if (MODE == 2) { Ah = d_g_hi;  Al = d_g_lo;  Bh = d_w1_hi;  Bl = d_w1_lo; }
    else                { Ah = d_h_hi;  Al = d_h_lo;  Bh = d_w2_hi;  Bl = d_w2_lo; }
    const __nv_bfloat16* srcs[4] = {Ah, Al, Bh, Bl};
    int rbase[4] = {row0, row0, col0, col0};

    float acc[4][4][4];
    #pragma unroll
    for (int mt = 0; mt < 4; mt++)
        #pragma unroll
        for (int nt = 0; nt < 4; nt++)
            #pragma unroll
            for (int e = 0; e < 4; e++) acc[mt][nt][e] = 0.0f;

    mma_mainloop<KDIM>(srcs, rbase, sb, tid, lane, warp_m, warp_n, acc);

    float* stage = reinterpret_cast<float*>(sm);

    #pragma unroll 1
    for (int g = 0; g < 4; g++) {
        int cb = g*32;
        if (warp_n == g) {
            #pragma unroll
            for (int mt = 0; mt < 4; mt++) {
                int r0 = warp_m*64 + mt*16 + (lane >> 2);
                #pragma unroll
                for (int nt = 0; nt < 4; nt++) {
                    int c0 = nt*8 + (lane & 3)*2;
                    stage[r0*33 + c0]     = acc[mt][nt][0];
                    stage[r0*33 + c0 + 1] = acc[mt][nt][1];
                    stage[(r0+8)*33 + c0]     = acc[mt][nt][2];
                    stage[(r0+8)*33 + c0 + 1] = acc[mt][nt][3];
                }
            }
        }
        __syncthreads();

        if (MODE == 1) {
            #pragma unroll 4
            for (int rr = 0; rr < 16; rr++) {
                int r = wid*16 + rr;
                d_Yt[(size_t)(row0 + r)*768 + col0 + cb + lane] = stage[r*33 + lane];
            }
        } else if (MODE == 2) {
            int gc = col0 + cb + lane;
            if (gc < Cc) {
                float c1v = d_c1[gc];
                #pragma unroll 4
                for (int rr = 0; rr < 16; rr++) {
                    int r = wid*16 + rr;
                    float v = fmaxf(stage[r*33 + lane] + c1v, 0.0f);
                    split_store(v, d_h_hi, d_h_lo, (size_t)(row0 + r)*Cc + gc);
                }
            }
            #pragma unroll
            for (int q = 0; q < 4; q++) {
                int cc = wid*4 + q;
                int gcb = col0 + cb + cc;
                if (gcb < Cc) {
                    float c1v = d_c1[gcb];
                    #pragma unroll
                    for (int it = 0; it < 4; it++) {
                        int r = it*32 + lane;
                        float v = fmaxf(stage[r*33 + cc] + c1v, 0.0f);
                        d_htT[(size_t)gcb*BNN + row0 + r] = v;
                    }
                }
            }
        } else {
            #pragma unroll
            for (int q = 0; q < 4; q++) {
                int cc = wid*4 + q;
                int gc = col0 + cb + cc;
                if (gc < Cc) {
                    float c2v = d_c2[gc];
                    #pragma unroll
                    for (int it = 0; it < 4; it++) {
                        int r = it*32 + lane;
                        int gr = row0 + r;
                        float v = fmaxf(stage[r*33 + cc] + c2v, 0.0f)
                                + d_htT[(size_t)gc*BNN + gr];
                        int b = gr / Nn, n = gr - b*Nn;
                        outp[((size_t)b*Cc + gc)*Nn + n] = v;
                    }
                }
            }
        }
        __syncthreads();
    }
}

// ---------------- top-9: threshold + candidate filter ----------------
__device__ __forceinline__ unsigned fkey32(float v) {
    unsigned u = __float_as_uint(v);
    return (u & 0x80000000u) ? ~u : (u | 0x80000000u);
}

#define TK_CAP 128

__global__ void __launch_bounds__(128) topk9()
{
    __shared__ unsigned long long kb_s[4][TK_CAP];
    int lane = threadIdx.x & 31;
    int w    = threadIdx.x >> 5;
    int row  = blockIdx.x*4 + w;
    if (row >= BNN) return;
    int b = row / Nn, n = row - b*Nn;
    const float* dr = d_dist + ((size_t)b*NP + n)*NP;
    unsigned long long* kb = kb_s[w];

    float mv = FLT_MAX;
    #pragma unroll
    for (int i = 0; i < 13; i++) {
        float4 v = reinterpret_cast<const float4*>(dr)[i*32 + lane];
        mv = fminf(mv, fminf(fminf(v.x, v.y), fminf(v.z, v.w)));
    }

    float tau = 0.0f;
    float mm = mv;
    #pragma unroll
    for (int r = 0; r < 9; r++) {
        float v = mm;
        #pragma unroll
        for (int off = 16; off; off >>= 1) v = fminf(v, __shfl_xor_sync(0xffffffffu, v, off));
        unsigned bl = __ballot_sync(0xffffffffu, mm == v);
        int src = __ffs(bl) - 1;
        if (lane == src) mm = FLT_MAX;
        tau = v;
    }

    int cnt = 0;
    #pragma unroll 1
    for (int i = 0; i < 13; i++) {
        float4 v = reinterpret_cast<const float4*>(dr)[i*32 + lane];
        int mbase = (i*32 + lane)*4;
        float vv[4] = {v.x, v.y, v.z, v.w};
        #pragma unroll
        for (int c = 0; c < 4; c++) {
            bool pr = (vv[c] <= tau);
            unsigned msk = __ballot_sync(0xffffffffu, pr);
            if (pr) {
                int pos = cnt + __popc(msk & ((1u << lane) - 1u));
                if (pos < TK_CAP)
                    kb[pos] = ((unsigned long long)fkey32(vv[c]) << 32) | (unsigned)(mbase + c);
            }
            cnt += __popc(msk);
        }
    }

    if (cnt <= TK_CAP) {
        #pragma unroll 1
        for (int r = 0; r < 9; r++) {
            unsigned long long best = ~0ULL;
            #pragma unroll
            for (int s = 0; s < 4; s++) {
                int pp = lane + s*32;
                if (pp < cnt) { unsigned long long k = kb[pp]; if (k < best) best = k; }
            }
            #pragma unroll
            for (int off = 16; off; off >>= 1) {
                unsigned long long o = __shfl_xor_sync(0xffffffffu, best, off);
                if (o < best) best = o;
            }
            #pragma unroll
            for (int s = 0; s < 4; s++) {
                int pp = lane + s*32;
                if (pp < cnt && kb[pp] == best) kb[pp] = ~0ULL;
            }
            if (lane == 0) d_nn[row*KK + r] = (int)(best & 0xffffffffu);
        }
    } else if (lane == 0) {
        unsigned long long bd[9];
        #pragma unroll
        for (int s = 0; s < 9; s++) bd[s] = ~0ULL;
        unsigned long long wk = ~0ULL; int ws = 0;
        for (int m2 = 0; m2 < NP; m2++) {
            unsigned long long k = ((unsigned long long)fkey32(dr[m2]) << 32) | (unsigned)m2;
            if (k < wk) {
                bd[ws] = k;
                wk = bd[0]; ws = 0;
                #pragma unroll
                for (int s = 1; s < 9; s++) if (bd[s] > wk) { wk = bd[s]; ws = s; }
            }
        }
        #pragma unroll
        for (int s = 0; s < 9; s++) d_nn[row*KK + s] = (int)(bd[s] & 0xffffffffu);
    }
}

// ---------------- g = relu(U + be + max_k V[idx]); emit bf16 split ----------------
__global__ void gather_max(const float* __restrict__ be)
{
    int j = blockIdx.x;
    int o = threadIdx.x;      // 384 threads
    int b = j / Nn;
    int base = b*Nn;
    int id[9];
    #pragma unroll
    for (int k = 0; k < 9; k++) id[k] = d_nn[j*9 + k];
    float m = -FLT_MAX;
    #pragma unroll
    for (int k = 0; k < 9; k++)
        m = fmaxf(m, d_Yt[(size_t)(base + id[k])*768 + 384 + o]);
    float u = d_Yt[(size_t)j*768 + o] + be[o];
    float v = fmaxf(u + m, 0.0f);
    split_store(v, d_g_hi, d_g_lo, (size_t)j*384 + o);
}

// ---------------- launch ----------------
extern "C" void kernel_launch(void* const* d_in, const int* in_sizes, int n_in,
                              void* d_out, int out_size)
{
    const float* x   = (const float*)d_in[0];
    const float* pos = (const float*)d_in[1];
    const float* We  = (const float*)d_in[2];
    const float* be  = (const float*)d_in[3];
    const float* W1  = (const float*)d_in[4];
    const float* b1  = (const float*)d_in[5];
    const float* g1  = (const float*)d_in[6];
    const float* bb1 = (const float*)d_in[7];
    const float* W2  = (const float*)d_in[8];
    const float* b2  = (const float*)d_in[9];
    const float* g2  = (const float*)d_in[10];
    const float* bb2 = (const float*)d_in[11];
    float* out = (float*)d_out;

    cudaFuncSetAttribute(mma_dist,    cudaFuncAttributeMaxDynamicSharedMemorySize, GSMEM);
    cudaFuncSetAttribute(mma_gemm<1>, cudaFuncAttributeMaxDynamicSharedMemorySize, GSMEM);
    cudaFuncSetAttribute(mma_gemm<2>, cudaFuncAttributeMaxDynamicSharedMemorySize, GSMEM);
    cudaFuncSetAttribute(mma_gemm<3>, cudaFuncAttributeMaxDynamicSharedMemorySize, GSMEM);

    prep_w<<<576, 256>>>(We, W1, b1, g1, bb1, W2, b2, g2, bb2);
    prep_xf<<<BNN, 192>>>(x, pos);
    pad_fill<<<Bz*(NP-Nn), 192>>>();
    { dim3 g(NBLK*(NBLK+1)/2, 1, Bz); mma_dist<<<g, 256, GSMEM>>>(); }
    topk9<<<(BNN+3)/4, 128>>>();
    { dim3 g(6, 98, 1);  mma_gemm<1><<<g, 256, GSMEM>>>(nullptr); }
    gather_max<<<BNN, 384>>>(be);
    { dim3 g(2, 98, 1);  mma_gemm<2><<<g, 256, GSMEM>>>(nullptr); }
    { dim3 g(2, 98, 1);  mma_gemm<3><<<g, 256, GSMEM>>>(out); }
}

// round 7
// speedup vs baseline: 3.2785x; 1.0425x over previous
#include <cuda_runtime.h>
#include <cuda_bf16.h>
#include <math.h>
#include <float.h>

#define Bz 8
#define Cc 192
#define Nn 1568
#define NP 1664            /* 13*128 */
#define BNN (Bz*Nn)        /* 12544 = 98*128 */
#define KK 9
#define NBLK 13
#define NPAIR (NBLK*(NBLK+1)/2)     /* 91 */
#define DIST_CTAS (NPAIR*Bz)        /* 728 */
#define G1_CTAS (6*98)              /* 588 */

// smem tile geometry for the MMA GEMM
#define BK 32
#define TROW_B 80                /* bytes per smem row: 40 bf16 (32 + 8 pad) */
#define TILE_B (128*TROW_B)      /* 10240 bytes per operand tile */
#define STAGE_B (4*TILE_B)       /* Ah, Al, Bh, Bl */
#define GSMEM (2*STAGE_B)        /* 81920 bytes */

// ---------------- scratch (static device globals; no allocation) ----------------
__device__ __align__(256) __nv_bfloat16 d_xn_hi[(size_t)Bz*NP*Cc], d_xn_lo[(size_t)Bz*NP*Cc];
__device__ __align__(256) __nv_bfloat16 d_xf_hi[(size_t)BNN*Cc],   d_xf_lo[(size_t)BNN*Cc];
__device__ __align__(256) float d_sqp[Bz*NP];
__device__ __align__(256) float d_dist[(size_t)Bz*NP*NP];
__device__ __align__(256) __nv_bfloat16 d_wuv_hi[768*Cc], d_wuv_lo[768*Cc];
__device__ __align__(256) __nv_bfloat16 d_w1_hi[256*384], d_w1_lo[256*384];
__device__ __align__(256) __nv_bfloat16 d_w2_hi[256*Cc],  d_w2_lo[256*Cc];
__device__ __align__(256) float d_c1[Cc], d_c2[Cc];
__device__ __align__(256) float d_Yt[(size_t)BNN*768];
__device__ __align__(256) __nv_bfloat16 d_g_hi[(size_t)BNN*384], d_g_lo[(size_t)BNN*384];
__device__ __align__(256) __nv_bfloat16 d_h_hi[(size_t)BNN*Cc],  d_h_lo[(size_t)BNN*Cc];
__device__ __align__(256) float d_htT[(size_t)Cc*BNN];     // shortcut, transposed [c][node]

// ---------------- PTX helpers ----------------
__device__ __forceinline__ unsigned smem_u32(const void* p) {
    unsigned a;
    asm("{ .reg .u64 t; cvta.to.shared.u64 t, %1; cvt.u32.u64 %0, t; }" : "=r"(a) : "l"(p));
    return a;
}
__device__ __forceinline__ void cpa16(unsigned s, const void* g) {
    asm volatile("cp.async.cg.shared.global [%0], [%1], 16;" :: "r"(s), "l"(g));
}
#define CP_COMMIT() asm volatile("cp.async.commit_group;" ::: "memory")
#define CP_WAIT(n)  asm volatile("cp.async.wait_group %0;" :: "n"(n) : "memory")

__device__ __forceinline__ void ldm4(unsigned* r, unsigned a) {
    asm volatile("ldmatrix.sync.aligned.m8n8.x4.shared.b16 {%0,%1,%2,%3}, [%4];"
        : "=r"(r[0]), "=r"(r[1]), "=r"(r[2]), "=r"(r[3]) : "r"(a));
}
__device__ __forceinline__ void mma_bf16(float* c, const unsigned* a, const unsigned* b) {
    asm volatile("mma.sync.aligned.m16n8k16.row.col.f32.bf16.bf16.f32 "
        "{%0,%1,%2,%3}, {%4,%5,%6,%7}, {%8,%9}, {%0,%1,%2,%3};"
        : "+f"(c[0]), "+f"(c[1]), "+f"(c[2]), "+f"(c[3])
        : "r"(a[0]), "r"(a[1]), "r"(a[2]), "r"(a[3]), "r"(b[0]), "r"(b[1]));
}

__device__ __forceinline__ void split_store(float v, __nv_bfloat16* hi, __nv_bfloat16* lo, size_t i) {
    __nv_bfloat16 h = __float2bfloat16(v);
    hi[i] = h;
    lo[i] = __float2bfloat16(v - __bfloat162float(h));
}

// ---------------- fused prep: xf blocks | weight blocks | pad blocks ----------------
__global__ void prep_all(const float* __restrict__ x, const float* __restrict__ pos,
                         const float* __restrict__ We, const float* __restrict__ W1,
                         const float* __restrict__ b1, const float* __restrict__ g1,
                         const float* __restrict__ bb1, const float* __restrict__ W2,
                         const float* __restrict__ b2, const float* __restrict__ g2,
                         const float* __restrict__ bb2)
{
    int blk = blockIdx.x;
    int c = threadIdx.x;              // 192 threads
    if (blk < BNN) {
        // ---- xf = x + pos^T, normalize, sq ----
        int j = blk;
        int b = j / Nn, n = j - b*Nn;
        float v = x[((size_t)b*Cc + c)*Nn + n] + pos[n*Cc + c];
        split_store(v, d_xf_hi, d_xf_lo, (size_t)j*Cc + c);

        __shared__ float red[Cc];
        __shared__ float s_nrm;
        red[c] = v*v;
        __syncthreads();
        if (c < 64) red[c] += red[c+64] + red[c+128];
        __syncthreads();
        if (c < 32) {
            float s = red[c] + red[c+32];
            #pragma unroll
            for (int o = 16; o; o >>= 1) s += __shfl_xor_sync(0xffffffffu, s, o);
            if (c == 0) s_nrm = fmaxf(sqrtf(s), 1e-12f);
        }
        __syncthreads();
        float xn = v / s_nrm;
        split_store(xn, d_xn_hi, d_xn_lo, ((size_t)b*NP + n)*Cc + c);

        red[c] = xn*xn;
        __syncthreads();
        if (c < 64) red[c] += red[c+64] + red[c+128];
        __syncthreads();
        if (c < 32) {
            float s = red[c] + red[c+32];
            #pragma unroll
            for (int o = 16; o; o >>= 1) s += __shfl_xor_sync(0xffffffffu, s, o);
            if (c == 0) d_sqp[b*NP + n] = s;
        }
    } else if (blk < BNN + 768) {
        // ---- weight folding + bf16 split ----
        int i = (blk - BNN)*192 + c;   // 0 .. 147455
        const float denom = (float)sqrt(1.0 + 1e-5);
        if (i < 768*Cc) {
            int o = i/Cc, cc = i - o*Cc;
            float v = (o < 384) ? (We[o*384 + cc] - We[o*384 + 192 + cc])
                                : We[(o-384)*384 + 192 + cc];
            split_store(v, d_wuv_hi, d_wuv_lo, i);
        }
        if (i < 256*384) {
            int o = i/384;
            float v = (o < 192) ? W1[i] * (g1[o]/denom) : 0.0f;
            split_store(v, d_w1_hi, d_w1_lo, i);
        }
        if (i < 256*192) {
            int o = i/192;
            float v = (o < 192) ? W2[i] * (g2[o]/denom) : 0.0f;
            split_store(v, d_w2_hi, d_w2_lo, i);
        }
        if (i < Cc) {
            d_c1[i] = b1[i]*(g1[i]/denom) + bb1[i];
            d_c2[i] = b2[i]*(g2[i]/denom) + bb2[i];
        }
    } else {
        // ---- pad rows of xn; sentinel sq ----
        int r = blk - BNN - 768;       // 0..767
        int b = r / (NP-Nn), pr = r - b*(NP-Nn);
        int row = Nn + pr;
        size_t i = ((size_t)b*NP + row)*Cc + c;
        d_xn_hi[i] = __float2bfloat16(0.0f);
        d_xn_lo[i] = __float2bfloat16(0.0f);
        if (c == 0) d_sqp[b*NP + row] = 1e30f;
    }
}

// ============ shared mainloop: computes 128x128 accs from Ah/Al vs Bh/Bl ============
template<int KDIM>
__device__ __forceinline__ void mma_mainloop(
    const __nv_bfloat16* const* srcs, const int* rbase,
    unsigned sb, int tid, int lane, int warp_m, int warp_n,
    float acc[4][4][4])
{
    constexpr int NCH = KDIM / BK;
    auto load_chunk = [&](int ch, int s) {
        unsigned so = sb + s*STAGE_B;
        int k0 = ch*BK;
        #pragma unroll
        for (int t = 0; t < 4; t++) {
            #pragma unroll
            for (int q = 0; q < 2; q++) {
                int v = tid + q*256;
                int row = v >> 2, c4 = v & 3;
                cpa16(so + t*TILE_B + row*TROW_B + c4*16,
                      srcs[t] + (size_t)(rbase[t] + row)*KDIM + k0 + c4*8);
            }
        }
    };

    load_chunk(0, 0);
    CP_COMMIT();

    #pragma unroll
    for (int ch = 0; ch < NCH; ch++) {
        if (ch + 1 < NCH) { load_chunk(ch+1, (ch+1)&1); CP_COMMIT(); CP_WAIT(1); }
        else              { CP_WAIT(0); }
        __syncthreads();

        unsigned so = sb + (ch&1)*STAGE_B;
        #pragma unroll
        for (int ks = 0; ks < 2; ks++) {
            unsigned ah[4][4], al[4][4], bh[4][2], bl[4][2];
            #pragma unroll
            for (int mt = 0; mt < 4; mt++) {
                unsigned ra = so + (warp_m*64 + mt*16 + (lane & 15))*TROW_B
                            + ks*32 + (lane >> 4)*16;
                ldm4(ah[mt], ra);
                ldm4(al[mt], ra + TILE_B);
            }
            #pragma unroll
            for (int p = 0; p < 2; p++) {
                int nrow = warp_n*32 + p*16 + (lane >> 4)*8 + (lane & 7);
                unsigned rb = so + 2*TILE_B + nrow*TROW_B + ks*32 + ((lane >> 3) & 1)*16;
                unsigned r4[4];
                ldm4(r4, rb);
                bh[2*p][0] = r4[0]; bh[2*p][1] = r4[1];
                bh[2*p+1][0] = r4[2]; bh[2*p+1][1] = r4[3];
                ldm4(r4, rb + TILE_B);
                bl[2*p][0] = r4[0]; bl[2*p][1] = r4[1];
                bl[2*p+1][0] = r4[2]; bl[2*p+1][1] = r4[3];
            }
            #pragma unroll
            for (int mt = 0; mt < 4; mt++)
                #pragma unroll
                for (int nt = 0; nt < 4; nt++) {
                    mma_bf16(acc[mt][nt], ah[mt], bh[nt]);
                    mma_bf16(acc[mt][nt], ah[mt], bl[nt]);
                    mma_bf16(acc[mt][nt], al[mt], bh[nt]);
                }
        }
        __syncthreads();
    }
}

// ---------------- phase1: dist (symmetric) + gemm1 (Yt) in ONE launch ----------------
__global__ void __launch_bounds__(256, 2) phase1()
{
    extern __shared__ char sm[];
    unsigned sb = smem_u32(sm);
    int tid = threadIdx.x, lane = tid & 31, wid = tid >> 5;
    int warp_m = wid & 1, warp_n = wid >> 1;
    int id = blockIdx.x;

    float acc[4][4][4];
    #pragma unroll
    for (int mt = 0; mt < 4; mt++)
        #pragma unroll
        for (int nt = 0; nt < 4; nt++)
            #pragma unroll
            for (int e = 0; e < 4; e++) acc[mt][nt][e] = 0.0f;

    float* stage = reinterpret_cast<float*>(sm);   // 128 x 33 floats

    if (id < DIST_CTAS) {
        // ---------- dist pair ----------
        int z = id / NPAIR;
        int p = id - z*NPAIR, by = 0;
        while (p >= NBLK - by) { p -= NBLK - by; by++; }
        int bx = by + p;
        int row0 = by*128, col0 = bx*128;

        size_t zo = (size_t)z*NP*Cc;
        const __nv_bfloat16* srcs[4] = {d_xn_hi + zo, d_xn_lo + zo, d_xn_hi + zo, d_xn_lo + zo};
        int rbase[4] = {row0, row0, col0, col0};
        mma_mainloop<Cc>(srcs, rbase, sb, tid, lane, warp_m, warp_n, acc);

        const float* sq = d_sqp + z*NP;
        float* dst = d_dist + (size_t)z*NP*NP;
        bool mirror = (bx != by);

        #pragma unroll 1
        for (int g = 0; g < 4; g++) {
            int cb = g*32;
            if (warp_n == g) {
                #pragma unroll
                for (int mt = 0; mt < 4; mt++) {
                    int r0 = warp_m*64 + mt*16 + (lane >> 2);
                    float s0 = sq[row0 + r0];
                    float s8 = sq[row0 + r0 + 8];
                    #pragma unroll
                    for (int nt = 0; nt < 4; nt++) {
                        int c0 = nt*8 + (lane & 3)*2;
                        stage[r0*33 + c0]     = s0 - 2.0f*acc[mt][nt][0];
                        stage[r0*33 + c0 + 1] = s0 - 2.0f*acc[mt][nt][1];
                        stage[(r0+8)*33 + c0]     = s8 - 2.0f*acc[mt][nt][2];
                        stage[(r0+8)*33 + c0 + 1] = s8 - 2.0f*acc[mt][nt][3];
                    }
                }
            }
            __syncthreads();
            {
                float sqc = sq[col0 + cb + lane];
                #pragma unroll 4
                for (int rr = 0; rr < 16; rr++) {
                    int r = wid*16 + rr;
                    dst[(size_t)(row0 + r)*NP + col0 + cb + lane] = stage[r*33 + lane] + sqc;
                }
            }
            if (mirror) {
                #pragma unroll
                for (int q = 0; q < 4; q++) {
                    int cc = wid*4 + q;
                    float sqc = sq[col0 + cb + cc];
                    #pragma unroll
                    for (int it = 0; it < 4; it++) {
                        int r = it*32 + lane;
                        dst[(size_t)(col0 + cb + cc)*NP + row0 + r] = stage[r*33 + cc] + sqc;
                    }
                }
            }
            __syncthreads();
        }
    } else {
        // ---------- gemm1: Yt = xf . WUV^T ----------
        int t = id - DIST_CTAS;
        int by = t / 6, bx = t - by*6;
        int row0 = by*128, col0 = bx*128;

        const __nv_bfloat16* srcs[4] = {d_xf_hi, d_xf_lo, d_wuv_hi, d_wuv_lo};
        int rbase[4] = {row0, row0, col0, col0};
        mma_mainloop<Cc>(srcs, rbase, sb, tid, lane, warp_m, warp_n, acc);

        #pragma unroll 1
        for (int g = 0; g < 4; g++) {
            int cb = g*32;
            if (warp_n == g) {
                #pragma unroll
                for (int mt = 0; mt < 4; mt++) {
                    int r0 = warp_m*64 + mt*16 + (lane >> 2);
                    #pragma unroll
                    for (int nt = 0; nt < 4; nt++) {
                        int c0 = nt*8 + (lane & 3)*2;
                        stage[r0*33 + c0]     = acc[mt][nt][0];
                        stage[r0*33 + c0 + 1] = acc[mt][nt][1];
                        stage[(r0+8)*33 + c0]     = acc[mt][nt][2];
                        stage[(r0+8)*33 + c0 + 1] = acc[mt][nt][3];
                    }
                }
            }
            __syncthreads();
            #pragma unroll 4
            for (int rr = 0; rr < 16; rr++) {
                int r = wid*16 + rr;
                d_Yt[(size_t)(row0 + r)*768 + col0 + cb + lane] = stage[r*33 + lane];
            }
            __syncthreads();
        }
    }
}

// ---------------- general GEMMs (modes 2..3) ----------------
// MODE 2: h  = relu(g . W1s^T + c1) -> split + htT   grid (2,98),   K=384
// MODE 3: out = relu(h . W2s^T + c2) + htT, scatter  grid (2,98),   K=192
template<int MODE>
__global__ void __launch_bounds__(256, 2) mma_gemm(float* __restrict__ outp)
{
    constexpr int KDIM = (MODE == 2) ? 384 : 192;

    extern __shared__ char sm[];
    unsigned sb = smem_u32(sm);
    int tid = threadIdx.x, lane = tid & 31, wid = tid >> 5;
    int warp_m = wid & 1, warp_n = wid >> 1;
    int bx = blockIdx.x, by = blockIdx.y;
    int row0 = by*128, col0 = bx*128;

    const __nv_bfloat16 *Ah, *Al, *Bh, *Bl;
    if (MODE == 2) { Ah = d_g_hi; Al = d_g_lo; Bh = d_w1_hi; Bl = d_w1_lo; }
    else           { Ah = d_h_hi; Al = d_h_lo; Bh = d_w2_hi; Bl = d_w2_lo; }
    const __nv_bfloat16* srcs[4] = {Ah, Al, Bh, Bl};
    int rbase[4] = {row0, row0, col0, col0};

    float acc[4][4][4];
    #pragma unroll
    for (int mt = 0; mt < 4; mt++)
        #pragma unroll
        for (int nt = 0; nt < 4; nt++)
            #pragma unroll
            for (int e = 0; e < 4; e++) acc[mt][nt][e] = 0.0f;

    mma_mainloop<KDIM>(srcs, rbase, sb, tid, lane, warp_m, warp_n, acc);

    float* stage = reinterpret_cast<float*>(sm);

    #pragma unroll 1
    for (int g = 0; g < 4; g++) {
        int cb = g*32;
        if (warp_n == g) {
            #pragma unroll
            for (int mt = 0; mt < 4; mt++) {
                int r0 = warp_m*64 + mt*16 + (lane >> 2);
                #pragma unroll
                for (int nt = 0; nt < 4; nt++) {
                    int c0 = nt*8 + (lane & 3)*2;
                    stage[r0*33 + c0]     = acc[mt][nt][0];
                    stage[r0*33 + c0 + 1] = acc[mt][nt][1];
                    stage[(r0+8)*33 + c0]     = acc[mt][nt][2];
                    stage[(r0+8)*33 + c0 + 1] = acc[mt][nt][3];
                }
            }
        }
        __syncthreads();

        if (MODE == 2) {
            int gc = col0 + cb + lane;
            if (gc < Cc) {
                float c1v = d_c1[gc];
                #pragma unroll 4
                for (int rr = 0; rr < 16; rr++) {
                    int r = wid*16 + rr;
                    float v = fmaxf(stage[r*33 + lane] + c1v, 0.0f);
                    split_store(v, d_h_hi, d_h_lo, (size_t)(row0 + r)*Cc + gc);
                }
            }
            #pragma unroll
            for (int q = 0; q < 4; q++) {
                int cc = wid*4 + q;
                int gcb = col0 + cb + cc;
                if (gcb < Cc) {
                    float c1v = d_c1[gcb];
                    #pragma unroll
                    for (int it = 0; it < 4; it++) {
                        int r = it*32 + lane;
                        float v = fmaxf(stage[r*33 + cc] + c1v, 0.0f);
                        d_htT[(size_t)gcb*BNN + row0 + r] = v;
                    }
                }
            }
        } else {
            #pragma unroll
            for (int q = 0; q < 4; q++) {
                int cc = wid*4 + q;
                int gc = col0 + cb + cc;
                if (gc < Cc) {
                    float c2v = d_c2[gc];
                    #pragma unroll
                    for (int it = 0; it < 4; it++) {
                        int r = it*32 + lane;
                        int gr = row0 + r;
                        float v = fmaxf(stage[r*33 + cc] + c2v, 0.0f)
                                + d_htT[(size_t)gc*BNN + gr];
                        int b = gr / Nn, n = gr - b*Nn;
                        outp[((size_t)b*Cc + gc)*Nn + n] = v;
                    }
                }
            }
        }
        __syncthreads();
    }
}

// ---------------- fused top-9 + gather_max ----------------
__device__ __forceinline__ unsigned fkey32(float v) {
    unsigned u = __float_as_uint(v);
    return (u & 0x80000000u) ? ~u : (u | 0x80000000u);
}

#define TK_CAP 128

__global__ void __launch_bounds__(128) topk_gather(const float* __restrict__ be)
{
    __shared__ unsigned long long kb_s[4][TK_CAP];
    __shared__ int ids[4][KK];
    int lane = threadIdx.x & 31;
    int w    = threadIdx.x >> 5;
    int row  = blockIdx.x*4 + w;
    int b = row / Nn, n = row - b*Nn;
    const float* dr = d_dist + ((size_t)b*NP + n)*NP;
    unsigned long long* kb = kb_s[w];

    // ---- pass 1: per-lane min ----
    float mv = FLT_MAX;
    #pragma unroll
    for (int i = 0; i < 13; i++) {
        float4 v = reinterpret_cast<const float4*>(dr)[i*32 + lane];
        mv = fminf(mv, fminf(fminf(v.x, v.y), fminf(v.z, v.w)));
    }

    // ---- tau = 9th smallest of 32 lane minima ----
    float tau = 0.0f;
    float mm = mv;
    #pragma unroll
    for (int r = 0; r < 9; r++) {
        float v = mm;
        #pragma unroll
        for (int off = 16; off; off >>= 1) v = fminf(v, __shfl_xor_sync(0xffffffffu, v, off));
        unsigned bl = __ballot_sync(0xffffffffu, mm == v);
        int src = __ffs(bl) - 1;
        if (lane == src) mm = FLT_MAX;
        tau = v;
    }

    // ---- pass 2: compact candidates ----
    int cnt = 0;
    #pragma unroll 1
    for (int i = 0; i < 13; i++) {
        float4 v = reinterpret_cast<const float4*>(dr)[i*32 + lane];
        int mbase = (i*32 + lane)*4;
        float vv[4] = {v.x, v.y, v.z, v.w};
        #pragma unroll
        for (int c = 0; c < 4; c++) {
            bool pr = (vv[c] <= tau);
            unsigned msk = __ballot_sync(0xffffffffu, pr);
            if (pr) {
                int pos = cnt + __popc(msk & ((1u << lane) - 1u));
                if (pos < TK_CAP)
                    kb[pos] = ((unsigned long long)fkey32(vv[c]) << 32) | (unsigned)(mbase + c);
            }
            cnt += __popc(msk);
        }
    }

    if (cnt <= TK_CAP) {
        #pragma unroll 1
        for (int r = 0; r < 9; r++) {
            unsigned long long best = ~0ULL;
            #pragma unroll
            for (int s = 0; s < 4; s++) {
                int pp = lane + s*32;
                if (pp < cnt) { unsigned long long k = kb[pp]; if (k < best) best = k; }
            }
            #pragma unroll
            for (int off = 16; off; off >>= 1) {
                unsigned long long o = __shfl_xor_sync(0xffffffffu, best, off);
                if (o < best) best = o;
            }
            #pragma unroll
            for (int s = 0; s < 4; s++) {
                int pp = lane + s*32;
                if (pp < cnt && kb[pp] == best) kb[pp] = ~0ULL;
            }
            if (lane == 0) ids[w][r] = (int)(best & 0xffffffffu);
        }
    } else if (lane == 0) {
        unsigned long long bd[9];
        #pragma unroll
        for (int s = 0; s < 9; s++) bd[s] = ~0ULL;
        unsigned long long wk = ~0ULL; int ws = 0;
        for (int m2 = 0; m2 < NP; m2++) {
            unsigned long long k = ((unsigned long long)fkey32(dr[m2]) << 32) | (unsigned)m2;
            if (k < wk) {
                bd[ws] = k;
                wk = bd[0]; ws = 0;
                #pragma unroll
                for (int s = 1; s < 9; s++) if (bd[s] > wk) { wk = bd[s]; ws = s; }
            }
        }
        #pragma unroll
        for (int s = 0; s < 9; s++) ids[w][s] = (int)(bd[s] & 0xffffffffu);
    }

    __syncthreads();

    // ---- gather phase: g = relu(U + be + max_k V[idx]) for the 4 rows ----
    int tid = threadIdx.x;
    #pragma unroll 1
    for (int rw = 0; rw < 4; rw++) {
        int j = blockIdx.x*4 + rw;
        int bb = j / Nn;
        int base = bb*Nn;
        int id2[9];
        #pragma unroll
        for (int k = 0; k < 9; k++) id2[k] = ids[rw][k];
        #pragma unroll
        for (int it = 0; it < 3; it++) {
            int o = it*128 + tid;
            float m = -FLT_MAX;
            #pragma unroll
            for (int k = 0; k < 9; k++)
                m = fmaxf(m, d_Yt[(size_t)(base + id2[k])*768 + 384 + o]);
            float u = d_Yt[(size_t)j*768 + o] + be[o];
            float v = fmaxf(u + m, 0.0f);
            split_store(v, d_g_hi, d_g_lo, (size_t)j*384 + o);
        }
    }
}

// ---------------- launch ----------------
extern "C" void kernel_launch(void* const* d_in, const int* in_sizes, int n_in,
                              void* d_out, int out_size)
{
    const float* x   = (const float*)d_in[0];
    const float* pos = (const float*)d_in[1];
    const float* We  = (const float*)d_in[2];
    const float* be  = (const float*)d_in[3];
    const float* W1  = (const float*)d_in[4];
    const float* b1  = (const float*)d_in[5];
    const float* g1  = (const float*)d_in[6];
    const float* bb1 = (const float*)d_in[7];
    const float* W2  = (const float*)d_in[8];
    const float* b2  = (const float*)d_in[9];
    const float* g2  = (const float*)d_in[10];
    const float* bb2 = (const float*)d_in[11];
    float* out = (float*)d_out;

    cudaFuncSetAttribute(phase1,      cudaFuncAttributeMaxDynamicSharedMemorySize, GSMEM);
    cudaFuncSetAttribute(mma_gemm<2>, cudaFuncAttributeMaxDynamicSharedMemorySize, GSMEM);
    cudaFuncSetAttribute(mma_gemm<3>, cudaFuncAttributeMaxDynamicSharedMemorySize, GSMEM);

    prep_all<<<BNN + 768 + Bz*(NP-Nn), 192>>>(x, pos, We, W1, b1, g1, bb1, W2, b2, g2, bb2);
    phase1<<<DIST_CTAS + G1_CTAS, 256, GSMEM>>>();
    topk_gather<<<BNN/4, 128>>>(be);
    { dim3 g(2, 98, 1); mma_gemm<2><<<g, 256, GSMEM>>>(nullptr); }
    { dim3 g(2, 98, 1); mma_gemm<3><<<g, 256, GSMEM>>>(out); }
}

// round 8
// speedup vs baseline: 3.3986x; 1.0366x over previous
#include <cuda_runtime.h>
#include <cuda_bf16.h>
#include <math.h>
#include <float.h>

#define Bz 8
#define Cc 192
#define Nn 1568
#define NP 1664            /* 13*128 */
#define BNN (Bz*Nn)        /* 12544 = 98*128 */
#define KK 9
#define NBLK 13
#define NPAIR (NBLK*(NBLK+1)/2)     /* 91 */
#define DIST_CTAS (NPAIR*Bz)        /* 728 */
#define G1_CTAS (6*98)              /* 588 */

// smem tile geometry for the MMA GEMM
#define BK 32
#define TROW_B 80                /* bytes per smem row: 40 bf16 (32 + 8 pad) */
#define TILE_B (128*TROW_B)      /* 10240 bytes per operand tile */
#define STAGE_B (4*TILE_B)       /* Ah, Al, Bh, Bl */
#define GSMEM (2*STAGE_B)        /* 81920 bytes */

// fused tail kernel smem: pipeline area + persistent split-h tiles (6 chunks x hi/lo)
#define OFF_A2H GSMEM
#define OFF_A2L (GSMEM + 6*TILE_B)
#define SM_TAIL (GSMEM + 12*TILE_B)   /* 204800 bytes */
#define B_STAGE (2*TILE_B)

// ---------------- scratch (static device globals; no allocation) ----------------
__device__ __align__(256) __nv_bfloat16 d_xn_hi[(size_t)Bz*NP*Cc], d_xn_lo[(size_t)Bz*NP*Cc];
__device__ __align__(256) __nv_bfloat16 d_xf_hi[(size_t)BNN*Cc],   d_xf_lo[(size_t)BNN*Cc];
__device__ __align__(256) float d_sqp[Bz*NP];
__device__ __align__(256) float d_dist[(size_t)Bz*NP*NP];
__device__ __align__(256) __nv_bfloat16 d_wuv_hi[768*Cc], d_wuv_lo[768*Cc];
__device__ __align__(256) __nv_bfloat16 d_w1_hi[256*384], d_w1_lo[256*384];
__device__ __align__(256) __nv_bfloat16 d_w2_hi[256*Cc],  d_w2_lo[256*Cc];
__device__ __align__(256) float d_c1[Cc], d_c2[Cc];
__device__ __align__(256) float d_Yt[(size_t)BNN*768];
__device__ __align__(256) __nv_bfloat16 d_g_hi[(size_t)BNN*384], d_g_lo[(size_t)BNN*384];

// ---------------- PTX helpers ----------------
__device__ __forceinline__ unsigned smem_u32(const void* p) {
    unsigned a;
    asm("{ .reg .u64 t; cvta.to.shared.u64 t, %1; cvt.u32.u64 %0, t; }" : "=r"(a) : "l"(p));
    return a;
}
__device__ __forceinline__ void cpa16(unsigned s, const void* g) {
    asm volatile("cp.async.cg.shared.global [%0], [%1], 16;" :: "r"(s), "l"(g));
}
#define CP_COMMIT() asm volatile("cp.async.commit_group;" ::: "memory")
#define CP_WAIT(n)  asm volatile("cp.async.wait_group %0;" :: "n"(n) : "memory")

__device__ __forceinline__ void ldm4(unsigned* r, unsigned a) {
    asm volatile("ldmatrix.sync.aligned.m8n8.x4.shared.b16 {%0,%1,%2,%3}, [%4];"
        : "=r"(r[0]), "=r"(r[1]), "=r"(r[2]), "=r"(r[3]) : "r"(a));
}
__device__ __forceinline__ void mma_bf16(float* c, const unsigned* a, const unsigned* b) {
    asm volatile("mma.sync.aligned.m16n8k16.row.col.f32.bf16.bf16.f32 "
        "{%0,%1,%2,%3}, {%4,%5,%6,%7}, {%8,%9}, {%0,%1,%2,%3};"
        : "+f"(c[0]), "+f"(c[1]), "+f"(c[2]), "+f"(c[3])
        : "r"(a[0]), "r"(a[1]), "r"(a[2]), "r"(a[3]), "r"(b[0]), "r"(b[1]));
}

__device__ __forceinline__ void split_store(float v, __nv_bfloat16* hi, __nv_bfloat16* lo, size_t i) {
    __nv_bfloat16 h = __float2bfloat16(v);
    hi[i] = h;
    lo[i] = __float2bfloat16(v - __bfloat162float(h));
}

// ---------------- fused prep: xf blocks | weight blocks | pad blocks ----------------
__global__ void prep_all(const float* __restrict__ x, const float* __restrict__ pos,
                         const float* __restrict__ We, const float* __restrict__ W1,
                         const float* __restrict__ b1, const float* __restrict__ g1,
                         const float* __restrict__ bb1, const float* __restrict__ W2,
                         const float* __restrict__ b2, const float* __restrict__ g2,
                         const float* __restrict__ bb2)
{
    int blk = blockIdx.x;
    int c = threadIdx.x;              // 192 threads
    if (blk < BNN) {
        int j = blk;
        int b = j / Nn, n = j - b*Nn;
        float v = x[((size_t)b*Cc + c)*Nn + n] + pos[n*Cc + c];
        split_store(v, d_xf_hi, d_xf_lo, (size_t)j*Cc + c);

        __shared__ float red[Cc];
        __shared__ float s_nrm;
        red[c] = v*v;
        __syncthreads();
        if (c < 64) red[c] += red[c+64] + red[c+128];
        __syncthreads();
        if (c < 32) {
            float s = red[c] + red[c+32];
            #pragma unroll
            for (int o = 16; o; o >>= 1) s += __shfl_xor_sync(0xffffffffu, s, o);
            if (c == 0) s_nrm = fmaxf(sqrtf(s), 1e-12f);
        }
        __syncthreads();
        float xn = v / s_nrm;
        split_store(xn, d_xn_hi, d_xn_lo, ((size_t)b*NP + n)*Cc + c);

        red[c] = xn*xn;
        __syncthreads();
        if (c < 64) red[c] += red[c+64] + red[c+128];
        __syncthreads();
        if (c < 32) {
            float s = red[c] + red[c+32];
            #pragma unroll
            for (int o = 16; o; o >>= 1) s += __shfl_xor_sync(0xffffffffu, s, o);
            if (c == 0) d_sqp[b*NP + n] = s;
        }
    } else if (blk < BNN + 768) {
        int i = (blk - BNN)*192 + c;
        const float denom = (float)sqrt(1.0 + 1e-5);
        if (i < 768*Cc) {
            int o = i/Cc, cc = i - o*Cc;
            float v = (o < 384) ? (We[o*384 + cc] - We[o*384 + 192 + cc])
                                : We[(o-384)*384 + 192 + cc];
            split_store(v, d_wuv_hi, d_wuv_lo, i);
        }
        if (i < 256*384) {
            int o = i/384;
            float v = (o < 192) ? W1[i] * (g1[o]/denom) : 0.0f;
            split_store(v, d_w1_hi, d_w1_lo, i);
        }
        if (i < 256*192) {
            int o = i/192;
            float v = (o < 192) ? W2[i] * (g2[o]/denom) : 0.0f;
            split_store(v, d_w2_hi, d_w2_lo, i);
        }
        if (i < Cc) {
            d_c1[i] = b1[i]*(g1[i]/denom) + bb1[i];
            d_c2[i] = b2[i]*(g2[i]/denom) + bb2[i];
        }
    } else {
        int r = blk - BNN - 768;
        int b = r / (NP-Nn), pr = r - b*(NP-Nn);
        int row = Nn + pr;
        size_t i = ((size_t)b*NP + row)*Cc + c;
        d_xn_hi[i] = __float2bfloat16(0.0f);
        d_xn_lo[i] = __float2bfloat16(0.0f);
        if (c == 0) d_sqp[b*NP + row] = 1e30f;
    }
}

// ============ shared mainloop: computes 128x128 accs from Ah/Al vs Bh/Bl ============
template<int KDIM>
__device__ __forceinline__ void mma_mainloop(
    const __nv_bfloat16* const* srcs, const int* rbase,
    unsigned sb, int tid, int lane, int warp_m, int warp_n,
    float acc[4][4][4])
{
    constexpr int NCH = KDIM / BK;
    auto load_chunk = [&](int ch, int s) {
        unsigned so = sb + s*STAGE_B;
        int k0 = ch*BK;
        #pragma unroll
        for (int t = 0; t < 4; t++) {
            #pragma unroll
            for (int q = 0; q < 2; q++) {
                int v = tid + q*256;
                int row = v >> 2, c4 = v & 3;
                cpa16(so + t*TILE_B + row*TROW_B + c4*16,
                      srcs[t] + (size_t)(rbase[t] + row)*KDIM + k0 + c4*8);
            }
        }
    };

    load_chunk(0, 0);
    CP_COMMIT();

    #pragma unroll
    for (int ch = 0; ch < NCH; ch++) {
        if (ch + 1 < NCH) { load_chunk(ch+1, (ch+1)&1); CP_COMMIT(); CP_WAIT(1); }
        else              { CP_WAIT(0); }
        __syncthreads();

        unsigned so = sb + (ch&1)*STAGE_B;
        #pragma unroll
        for (int ks = 0; ks < 2; ks++) {
            unsigned ah[4][4], al[4][4], bh[4][2], bl[4][2];
            #pragma unroll
            for (int mt = 0; mt < 4; mt++) {
                unsigned ra = so + (warp_m*64 + mt*16 + (lane & 15))*TROW_B
                            + ks*32 + (lane >> 4)*16;
                ldm4(ah[mt], ra);
                ldm4(al[mt], ra + TILE_B);
            }
            #pragma unroll
            for (int p = 0; p < 2; p++) {
                int nrow = warp_n*32 + p*16 + (lane >> 4)*8 + (lane & 7);
                unsigned rb = so + 2*TILE_B + nrow*TROW_B + ks*32 + ((lane >> 3) & 1)*16;
                unsigned r4[4];
                ldm4(r4, rb);
                bh[2*p][0] = r4[0]; bh[2*p][1] = r4[1];
                bh[2*p+1][0] = r4[2]; bh[2*p+1][1] = r4[3];
                ldm4(r4, rb + TILE_B);
                bl[2*p][0] = r4[0]; bl[2*p][1] = r4[1];
                bl[2*p+1][0] = r4[2]; bl[2*p+1][1] = r4[3];
            }
            #pragma unroll
            for (int mt = 0; mt < 4; mt++)
                #pragma unroll
                for (int nt = 0; nt < 4; nt++) {
                    mma_bf16(acc[mt][nt], ah[mt], bh[nt]);
                    mma_bf16(acc[mt][nt], ah[mt], bl[nt]);
                    mma_bf16(acc[mt][nt], al[mt], bh[nt]);
                }
        }
        __syncthreads();
    }
}

// ---------------- phase1: dist (symmetric) + gemm1 (Yt) in ONE launch ----------------
__global__ void __launch_bounds__(256, 2) phase1()
{
    extern __shared__ char sm[];
    unsigned sb = smem_u32(sm);
    int tid = threadIdx.x, lane = tid & 31, wid = tid >> 5;
    int warp_m = wid & 1, warp_n = wid >> 1;
    int id = blockIdx.x;

    float acc[4][4][4];
    #pragma unroll
    for (int mt = 0; mt < 4; mt++)
        #pragma unroll
        for (int nt = 0; nt < 4; nt++)
            #pragma unroll
            for (int e = 0; e < 4; e++) acc[mt][nt][e] = 0.0f;

    float* stage = reinterpret_cast<float*>(sm);   // 128 x 33 floats

    if (id < DIST_CTAS) {
        int z = id / NPAIR;
        int p = id - z*NPAIR, by = 0;
        while (p >= NBLK - by) { p -= NBLK - by; by++; }
        int bx = by + p;
        int row0 = by*128, col0 = bx*128;

        size_t zo = (size_t)z*NP*Cc;
        const __nv_bfloat16* srcs[4] = {d_xn_hi + zo, d_xn_lo + zo, d_xn_hi + zo, d_xn_lo + zo};
        int rbase[4] = {row0, row0, col0, col0};
        mma_mainloop<Cc>(srcs, rbase, sb, tid, lane, warp_m, warp_n, acc);

        const float* sq = d_sqp + z*NP;
        float* dst = d_dist + (size_t)z*NP*NP;
        bool mirror = (bx != by);

        #pragma unroll 1
        for (int g = 0; g < 4; g++) {
            int cb = g*32;
            if (warp_n == g) {
                #pragma unroll
                for (int mt = 0; mt < 4; mt++) {
                    int r0 = warp_m*64 + mt*16 + (lane >> 2);
                    float s0 = sq[row0 + r0];
                    float s8 = sq[row0 + r0 + 8];
                    #pragma unroll
                    for (int nt = 0; nt < 4; nt++) {
                        int c0 = nt*8 + (lane & 3)*2;
                        stage[r0*33 + c0]     = s0 - 2.0f*acc[mt][nt][0];
                        stage[r0*33 + c0 + 1] = s0 - 2.0f*acc[mt][nt][1];
                        stage[(r0+8)*33 + c0]     = s8 - 2.0f*acc[mt][nt][2];
                        stage[(r0+8)*33 + c0 + 1] = s8 - 2.0f*acc[mt][nt][3];
                    }
                }
            }
            __syncthreads();
            {
                float sqc = sq[col0 + cb + lane];
                #pragma unroll 4
                for (int rr = 0; rr < 16; rr++) {
                    int r = wid*16 + rr;
                    dst[(size_t)(row0 + r)*NP + col0 + cb + lane] = stage[r*33 + lane] + sqc;
                }
            }
            if (mirror) {
                #pragma unroll
                for (int q = 0; q < 4; q++) {
                    int cc = wid*4 + q;
                    float sqc = sq[col0 + cb + cc];
                    #pragma unroll
                    for (int it = 0; it < 4; it++) {
                        int r = it*32 + lane;
                        dst[(size_t)(col0 + cb + cc)*NP + row0 + r] = stage[r*33 + cc] + sqc;
                    }
                }
            }
            __syncthreads();
        }
    } else {
        int t = id - DIST_CTAS;
        int by = t / 6, bx = t - by*6;
        int row0 = by*128, col0 = bx*128;

        const __nv_bfloat16* srcs[4] = {d_xf_hi, d_xf_lo, d_wuv_hi, d_wuv_lo};
        int rbase[4] = {row0, row0, col0, col0};
        mma_mainloop<Cc>(srcs, rbase, sb, tid, lane, warp_m, warp_n, acc);

        #pragma unroll 1
        for (int g = 0; g < 4; g++) {
            int cb = g*32;
            if (warp_n == g) {
                #pragma unroll
                for (int mt = 0; mt < 4; mt++) {
                    int r0 = warp_m*64 + mt*16 + (lane >> 2);
                    #pragma unroll
                    for (int nt = 0; nt < 4; nt++) {
                        int c0 = nt*8 + (lane & 3)*2;
                        stage[r0*33 + c0]     = acc[mt][nt][0];
                        stage[r0*33 + c0 + 1] = acc[mt][nt][1];
                        stage[(r0+8)*33 + c0]     = acc[mt][nt][2];
                        stage[(r0+8)*33 + c0 + 1] = acc[mt][nt][3];
                    }
                }
            }
            __syncthreads();
            #pragma unroll 4
            for (int rr = 0; rr < 16; rr++) {
                int r = wid*16 + rr;
                d_Yt[(size_t)(row0 + r)*768 + col0 + cb + lane] = stage[r*33 + lane];
            }
            __syncthreads();
        }
    }
}

// ---------------- fused tail: h = relu(g.W1^T+c1); out = relu(h.W2^T+c2)+h ----------------
__global__ void __launch_bounds__(256) mma_tail(float* __restrict__ outp)
{
    extern __shared__ char sm[];
    unsigned sb = smem_u32(sm);
    int tid = threadIdx.x, lane = tid & 31, wid = tid >> 5;
    int warp_m = wid & 1, warp_n = wid >> 1;
    int row0 = blockIdx.x*128;

    float acc[4][4][4];
    float* stage = reinterpret_cast<float*>(sm);

    // ================= phase A: h, two 128-col passes, K=384 =================
    #pragma unroll 1
    for (int p = 0; p < 2; p++) {
        #pragma unroll
        for (int mt = 0; mt < 4; mt++)
            #pragma unroll
            for (int nt = 0; nt < 4; nt++)
                #pragma unroll
                for (int e = 0; e < 4; e++) acc[mt][nt][e] = 0.0f;

        const __nv_bfloat16* srcs[4] = {d_g_hi, d_g_lo, d_w1_hi, d_w1_lo};
        int rbase[4] = {row0, row0, p*128, p*128};
        mma_mainloop<384>(srcs, rbase, sb, tid, lane, warp_m, warp_n, acc);

        // convert fragments -> persistent split-h smem tiles (ldmatrix A format)
        #pragma unroll
        for (int mt = 0; mt < 4; mt++) {
            int r0 = warp_m*64 + mt*16 + (lane >> 2);
            #pragma unroll
            for (int nt = 0; nt < 4; nt++) {
                int c0 = warp_n*32 + nt*8 + (lane & 3)*2;
                #pragma unroll
                for (int e = 0; e < 4; e++) {
                    int r  = r0 + ((e >> 1) << 3);
                    int gc = p*128 + c0 + (e & 1);
                    if (gc < Cc) {
                        float v = fmaxf(acc[mt][nt][e] + d_c1[gc], 0.0f);
                        __nv_bfloat16 hh = __float2bfloat16(v);
                        unsigned off = (unsigned)(gc >> 5)*TILE_B + r*TROW_B + (gc & 31)*2;
                        *reinterpret_cast<__nv_bfloat16*>(sm + OFF_A2H + off) = hh;
                        *reinterpret_cast<__nv_bfloat16*>(sm + OFF_A2L + off) =
                            __float2bfloat16(v - __bfloat162float(hh));
                    }
                }
            }
        }
        __syncthreads();
    }

    // ================= phase B: out, two 128-col passes, K=192, A from smem ==========
    #pragma unroll 1
    for (int p = 0; p < 2; p++) {
        #pragma unroll
        for (int mt = 0; mt < 4; mt++)
            #pragma unroll
            for (int nt = 0; nt < 4; nt++)
                #pragma unroll
                for (int e = 0; e < 4; e++) acc[mt][nt][e] = 0.0f;

        int colbase = p*128;
        auto load_B2 = [&](int ch, int s) {
            unsigned so = sb + s*B_STAGE;
            int k0 = ch*BK;
            const __nv_bfloat16* bs[2] = {d_w2_hi, d_w2_lo};
            #pragma unroll
            for (int t = 0; t < 2; t++) {
                #pragma unroll
                for (int q = 0; q < 2; q++) {
                    int v = tid + q*256;
                    int row = v >> 2, c4 = v & 3;
                    cpa16(so + t*TILE_B + row*TROW_B + c4*16,
                          bs[t] + (size_t)(colbase + row)*Cc + k0 + c4*8);
                }
            }
        };

        load_B2(0, 0);
        CP_COMMIT();

        #pragma unroll
        for (int ch = 0; ch < 6; ch++) {
            if (ch + 1 < 6) { load_B2(ch+1, (ch+1)&1); CP_COMMIT(); CP_WAIT(1); }
            else            { CP_WAIT(0); }
            __syncthreads();

            unsigned sob = sb + (ch&1)*B_STAGE;
            unsigned soa = sb + OFF_A2H - 0 + (unsigned)ch*TILE_B;   // hi base for this chunk
            #pragma unroll
            for (int ks = 0; ks < 2; ks++) {
                unsigned ah[4][4], al[4][4], bh[4][2], bl[4][2];
                #pragma unroll
                for (int mt = 0; mt < 4; mt++) {
                    unsigned ra = soa + (warp_m*64 + mt*16 + (lane & 15))*TROW_B
                                + ks*32 + (lane >> 4)*16;
                    ldm4(ah[mt], ra);
                    ldm4(al[mt], ra + 6*TILE_B);        // lo tiles sit 6*TILE_B above hi
                }
                #pragma unroll
                for (int q = 0; q < 2; q++) {
                    int nrow = warp_n*32 + q*16 + (lane >> 4)*8 + (lane & 7);
                    unsigned rb = sob + nrow*TROW_B + ks*32 + ((lane >> 3) & 1)*16;
                    unsigned r4[4];
                    ldm4(r4, rb);
                    bh[2*q][0] = r4[0]; bh[2*q][1] = r4[1];
                    bh[2*q+1][0] = r4[2]; bh[2*q+1][1] = r4[3];
                    ldm4(r4, rb + TILE_B);
                    bl[2*q][0] = r4[0]; bl[2*q][1] = r4[1];
                    bl[2*q+1][0] = r4[2]; bl[2*q+1][1] = r4[3];
                }
                #pragma unroll
                for (int mt = 0; mt < 4; mt++)
                    #pragma unroll
                    for (int nt = 0; nt < 4; nt++) {
                        mma_bf16(acc[mt][nt], ah[mt], bh[nt]);
                        mma_bf16(acc[mt][nt], ah[mt], bl[nt]);
                        mma_bf16(acc[mt][nt], al[mt], bh[nt]);
                    }
            }
            __syncthreads();
        }

        // epilogue: stage transpose, add c2, relu, add shortcut (hi+lo from smem), scatter
        #pragma unroll 1
        for (int g = 0; g < 4; g++) {
            int cb = g*32;
            if (warp_n == g) {
                #pragma unroll
                for (int mt = 0; mt < 4; mt++) {
                    int r0 = warp_m*64 + mt*16 + (lane >> 2);
                    #pragma unroll
                    for (int nt = 0; nt < 4; nt++) {
                        int c0 = nt*8 + (lane & 3)*2;
                        stage[r0*33 + c0]     = acc[mt][nt][0];
                        stage[r0*33 + c0 + 1] = acc[mt][nt][1];
                        stage[(r0+8)*33 + c0]     = acc[mt][nt][2];
                        stage[(r0+8)*33 + c0 + 1] = acc[mt][nt][3];
                    }
                }
            }
            __syncthreads();
            #pragma unroll
            for (int q = 0; q < 4; q++) {
                int cc = wid*4 + q;
                int gc = colbase + cb + cc;
                if (gc < Cc) {
                    float c2v = d_c2[gc];
                    unsigned ob = (unsigned)(gc >> 5)*TILE_B + (gc & 31)*2;
                    #pragma unroll
                    for (int it = 0; it < 4; it++) {
                        int r = it*32 + lane;
                        int gr = row0 + r;
                        unsigned off = ob + r*TROW_B;
                        float sc = __bfloat162float(*reinterpret_cast<__nv_bfloat16*>(sm + OFF_A2H + off))
                                 + __bfloat162float(*reinterpret_cast<__nv_bfloat16*>(sm + OFF_A2L + off));
                        float v = fmaxf(stage[r*33 + cc] + c2v, 0.0f) + sc;
                        int b = gr / Nn, n = gr - b*Nn;
                        outp[((size_t)b*Cc + gc)*Nn + n] = v;
                    }
                }
            }
            __syncthreads();
        }
    }
}

// ---------------- fused top-9 + gather_max ----------------
__device__ __forceinline__ unsigned fkey32(float v) {
    unsigned u = __float_as_uint(v);
    return (u & 0x80000000u) ? ~u : (u | 0x80000000u);
}

#define TK_CAP 128

__global__ void __launch_bounds__(128) topk_gather(const float* __restrict__ be)
{
    __shared__ unsigned long long kb_s[4][TK_CAP];
    __shared__ int ids[4][KK];
    int lane = threadIdx.x & 31;
    int w    = threadIdx.x >> 5;
    int row  = blockIdx.x*4 + w;
    int b = row / Nn, n = row - b*Nn;
    const float* dr = d_dist + ((size_t)b*NP + n)*NP;
    unsigned long long* kb = kb_s[w];

    float mv = FLT_MAX;
    #pragma unroll
    for (int i = 0; i < 13; i++) {
        float4 v = reinterpret_cast<const float4*>(dr)[i*32 + lane];
        mv = fminf(mv, fminf(fminf(v.x, v.y), fminf(v.z, v.w)));
    }

    float tau = 0.0f;
    float mm = mv;
    #pragma unroll
    for (int r = 0; r < 9; r++) {
        float v = mm;
        #pragma unroll
        for (int off = 16; off; off >>= 1) v = fminf(v, __shfl_xor_sync(0xffffffffu, v, off));
        unsigned bl = __ballot_sync(0xffffffffu, mm == v);
        int src = __ffs(bl) - 1;
        if (lane == src) mm = FLT_MAX;
        tau = v;
    }

    int cnt = 0;
    #pragma unroll 1
    for (int i = 0; i < 13; i++) {
        float4 v = reinterpret_cast<const float4*>(dr)[i*32 + lane];
        int mbase = (i*32 + lane)*4;
        float vv[4] = {v.x, v.y, v.z, v.w};
        #pragma unroll
        for (int c = 0; c < 4; c++) {
            bool pr = (vv[c] <= tau);
            unsigned msk = __ballot_sync(0xffffffffu, pr);
            if (pr) {
                int pos = cnt + __popc(msk & ((1u << lane) - 1u));
                if (pos < TK_CAP)
                    kb[pos] = ((unsigned long long)fkey32(vv[c]) << 32) | (unsigned)(mbase + c);
            }
            cnt += __popc(msk);
        }
    }

    if (cnt <= TK_CAP) {
        #pragma unroll 1
        for (int r = 0; r < 9; r++) {
            unsigned long long best = ~0ULL;
            #pragma unroll
            for (int s = 0; s < 4; s++) {
                int pp = lane + s*32;
                if (pp < cnt) { unsigned long long k = kb[pp]; if (k < best) best = k; }
            }
            #pragma unroll
            for (int off = 16; off; off >>= 1) {
                unsigned long long o = __shfl_xor_sync(0xffffffffu, best, off);
                if (o < best) best = o;
            }
            #pragma unroll
            for (int s = 0; s < 4; s++) {
                int pp = lane + s*32;
                if (pp < cnt && kb[pp] == best) kb[pp] = ~0ULL;
            }
            if (lane == 0) ids[w][r] = (int)(best & 0xffffffffu);
        }
    } else if (lane == 0) {
        unsigned long long bd[9];
        #pragma unroll
        for (int s = 0; s < 9; s++) bd[s] = ~0ULL;
        unsigned long long wk = ~0ULL; int ws = 0;
        for (int m2 = 0; m2 < NP; m2++) {
            unsigned long long k = ((unsigned long long)fkey32(dr[m2]) << 32) | (unsigned)m2;
            if (k < wk) {
                bd[ws] = k;
                wk = bd[0]; ws = 0;
                #pragma unroll
                for (int s = 1; s < 9; s++) if (bd[s] > wk) { wk = bd[s]; ws = s; }
            }
        }
        #pragma unroll
        for (int s = 0; s < 9; s++) ids[w][s] = (int)(bd[s] & 0xffffffffu);
    }

    __syncthreads();

    int tid = threadIdx.x;
    #pragma unroll 1
    for (int rw = 0; rw < 4; rw++) {
        int j = blockIdx.x*4 + rw;
        int bb = j / Nn;
        int base = bb*Nn;
        int id2[9];
        #pragma unroll
        for (int k = 0; k < 9; k++) id2[k] = ids[rw][k];
        #pragma unroll
        for (int it = 0; it < 3; it++) {
            int o = it*128 + tid;
            float m = -FLT_MAX;
            #pragma unroll
            for (int k = 0; k < 9; k++)
                m = fmaxf(m, d_Yt[(size_t)(base + id2[k])*768 + 384 + o]);
            float u = d_Yt[(size_t)j*768 + o] + be[o];
            float v = fmaxf(u + m, 0.0f);
            split_store(v, d_g_hi, d_g_lo, (size_t)j*384 + o);
        }
    }
}

// ---------------- launch ----------------
extern "C" void kernel_launch(void* const* d_in, const int* in_sizes, int n_in,
                              void* d_out, int out_size)
{
    const float* x   = (const float*)d_in[0];
    const float* pos = (const float*)d_in[1];
    const float* We  = (const float*)d_in[2];
    const float* be  = (const float*)d_in[3];
    const float* W1  = (const float*)d_in[4];
    const float* b1  = (const float*)d_in[5];
    const float* g1  = (const float*)d_in[6];
    const float* bb1 = (const float*)d_in[7];
    const float* W2  = (const float*)d_in[8];
    const float* b2  = (const float*)d_in[9];
    const float* g2  = (const float*)d_in[10];
    const float* bb2 = (const float*)d_in[11];
    float* out = (float*)d_out;

    cudaFuncSetAttribute(phase1,   cudaFuncAttributeMaxDynamicSharedMemorySize, GSMEM);
    cudaFuncSetAttribute(mma_tail, cudaFuncAttributeMaxDynamicSharedMemorySize, SM_TAIL);

    prep_all<<<BNN + 768 + Bz*(NP-Nn), 192>>>(x, pos, We, W1, b1, g1, bb1, W2, b2, g2, bb2);
    phase1<<<DIST_CTAS + G1_CTAS, 256, GSMEM>>>();
    topk_gather<<<BNN/4, 128>>>(be);
    mma_tail<<<98, 256, SM_TAIL>>>(out);
}